// round 11
// baseline (speedup 1.0000x reference)
#include <cuda_runtime.h>
#include <cstdint>

// Problem constants
#define BB     128
#define NNODE  512
#define KD     512          // IN == HID == 512 (contraction dim)
#define HD     512
#define JD     3072         // 1536 bilinear (g,p,r) + 1536 linear (g,h)
#define NTOT   (BB * NNODE) // 65536 nodes

// SIMT GEMM tile config (fallback pass only)
#define BM     64
#define BN     128
#define BKT    16

// Persistent kernel shape
#define NCTA   148
#define TLB    512          // threads per block in tree_lstm (16 warps)

// Tensor-core GEMM tile (tf32)
#define LTM    128
#define LTN    128
#define LKC    32                 // K elements per chunk = 128 bytes (tf32)
#define LCHUNKS (KD / LKC)        // 16
#define NTN    (JD / LTN)         // 24 column tiles
#define TILEB  16384              // one 128x128B SMEM tile
#define DSMEM_BYTES (4 * TILEB + 1024)
// idesc: dtype F32=1 @bit4, atype TF32=2 @bit7, btype TF32=2 @bit10, N/8 @bit17, M/16 @bit24
#define LIDESC ((1u << 4) | (2u << 7) | (2u << 10) | ((LTN / 8u) << 17) | ((LTM / 16u) << 24))

// tcgen05 is only legal in the arch-SPECIFIC (sm_103a) compilation pass. The
// harness also runs a plain compute_103 ptxas pass, which rejects tcgen05
// outright — so every tcgen05 token must vanish from that pass.
#if defined(__CUDA_ARCH_FEAT_SM103_ALL) || defined(__CUDA_ARCH_FEAT_SM100_ALL) || \
    (defined(__CUDA_ARCH_SPECIFIC__) && (__CUDA_ARCH_SPECIFIC__ == 1030))
#define HAS_TCGEN05 1
#else
#define HAS_TCGEN05 0
#endif

// ---------------- device globals (no runtime allocation allowed) -------------
__device__ float g_left[(size_t)NTOT * JD];   // left projections, by node id
__device__ float g_rw[(size_t)NTOT * JD];     // right projections, BY NODE ID (dedup)
__device__ float g_c[(size_t)NTOT * HD];      // cell state, by node id
__device__ float g_wlt[KD * JD];              // Wleft  transposed [k][j] (SIMT fallback)
__device__ float g_wrt[KD * JD];              // Wright transposed [k][j] (SIMT fallback)
__device__ unsigned short g_lvl[NTOT];
__device__ unsigned char g_haschild[NTOT];
__device__ int g_count[NNODE];
__device__ int g_off[NNODE + 1];
__device__ int g_cursor[NNODE];
__device__ int g_icount[NNODE];
__device__ int g_ioff[NNODE + 1];
__device__ int g_icursor[NNODE];
__device__ int g_nlev;
__device__ unsigned g_nodeid[NTOT];           // worklist: flat node id b*N+t
__device__ int g_parid[NTOT];                 // worklist: flat parent id, -1 = root
__device__ int g_iwork[NTOT];                 // internal-node worklist (by level)
__device__ unsigned g_bar_count;              // grid barrier (self-resetting)
__device__ unsigned g_bar_epoch;              // monotonic across replays

// ---------------- generic PTX helpers (legal on all passes) -------------------
__device__ __forceinline__ uint32_t smem_u32(const void* p) {
    uint32_t a;
    asm("{ .reg .u64 t; cvta.to.shared.u64 t, %1; cvt.u32.u64 %0, t; }" : "=r"(a) : "l"(p));
    return a;
}
#define SMEM_SWIZZLE_128B(o) ((o) ^ (((o) >> 3) & 0x70))

#if HAS_TCGEN05
__device__ __forceinline__ uint32_t elect_one_pred() {
    uint32_t p;
    asm volatile("{ .reg .pred p; elect.sync _|p, 0xFFFFFFFF; selp.b32 %0, 1, 0, p; }" : "=r"(p));
    return p;
}
__device__ __forceinline__ uint32_t to_tf32(float x) {
    uint32_t r; asm("cvt.rna.tf32.f32 %0, %1;" : "=r"(r) : "f"(x)); return r;
}

static constexpr uint64_t SMEM_DESC_BASE_SW128 =
    (uint64_t(2) << 61) | (uint64_t(1) << 46) | (uint64_t(64) << 32) | (uint64_t(1) << 16);
#define MAKE_SMEM_DESC(base) (SMEM_DESC_BASE_SW128 | ((uint64_t)((base) >> 4) & 0x3FFF))

#define TCGEN05_ALLOC(sres, n) \
    asm volatile("tcgen05.alloc.cta_group::1.sync.aligned.shared::cta.b32 [%0], %1;" \
                 :: "r"((uint32_t)(sres)), "r"((uint32_t)(n)) : "memory")
#define TCGEN05_DEALLOC(t, n) \
    asm volatile("tcgen05.dealloc.cta_group::1.sync.aligned.b32 %0, %1;" :: "r"(t), "r"((uint32_t)(n)))
#define TCGEN05_RELINQ() \
    asm volatile("tcgen05.relinquish_alloc_permit.cta_group::1.sync.aligned;")
#define TCGEN05_COMMIT(mb) \
    asm volatile("tcgen05.commit.cta_group::1.mbarrier::arrive::one.shared::cluster.b64 [%0];" \
                 :: "r"((uint32_t)(mb)) : "memory")
#define TCGEN05_FENCE_AFTER()  asm volatile("tcgen05.fence::after_thread_sync;" ::: "memory")
#define TCGEN05_FENCE_BEFORE() asm volatile("tcgen05.fence::before_thread_sync;" ::: "memory")
#define TCGEN05_WAIT_LD()      asm volatile("tcgen05.wait::ld.sync.aligned;" ::: "memory")
#define FENCE_PROXY_ASYNC()    asm volatile("fence.proxy.async.shared::cta;" ::: "memory")
#define MBARRIER_INIT(mb, c) \
    asm volatile("mbarrier.init.shared.b64 [%0], %1;" :: "r"((uint32_t)(mb)), "r"((uint32_t)(c)) : "memory")
#define MBARRIER_WAIT_PARITY(mb, ph) do { \
    uint32_t _m = (uint32_t)(mb), _p = (uint32_t)(ph), _d; \
    asm volatile("{ .reg .pred p; mbarrier.try_wait.parity.acquire.cta.shared::cta.b64 p, [%1], %2; selp.b32 %0, 1, 0, p; }" \
                 : "=r"(_d) : "r"(_m), "r"(_p) : "memory"); \
    if (!_d) { \
        asm volatile("{ .reg .pred P1; WL_%=: mbarrier.try_wait.parity.acquire.cta.shared::cta.b64 P1, [%0], %1, 0x989680; @P1 bra.uni WD_%=; bra.uni WL_%=; WD_%=: }" \
                     :: "r"(_m), "r"(_p) : "memory"); \
    } } while (0)

#define TCGEN05_LD_32X32B_X32(r, addr) \
    asm volatile("tcgen05.ld.sync.aligned.32x32b.x32.b32 " \
        "{%0, %1, %2, %3, %4, %5, %6, %7, %8, %9, %10, %11, %12, %13, %14, %15, " \
        " %16, %17, %18, %19, %20, %21, %22, %23, %24, %25, %26, %27, %28, %29, %30, %31}, [%32];" \
        : "=r"((r)[0]),  "=r"((r)[1]),  "=r"((r)[2]),  "=r"((r)[3]), \
          "=r"((r)[4]),  "=r"((r)[5]),  "=r"((r)[6]),  "=r"((r)[7]), \
          "=r"((r)[8]),  "=r"((r)[9]),  "=r"((r)[10]), "=r"((r)[11]), \
          "=r"((r)[12]), "=r"((r)[13]), "=r"((r)[14]), "=r"((r)[15]), \
          "=r"((r)[16]), "=r"((r)[17]), "=r"((r)[18]), "=r"((r)[19]), \
          "=r"((r)[20]), "=r"((r)[21]), "=r"((r)[22]), "=r"((r)[23]), \
          "=r"((r)[24]), "=r"((r)[25]), "=r"((r)[26]), "=r"((r)[27]), \
          "=r"((r)[28]), "=r"((r)[29]), "=r"((r)[30]), "=r"((r)[31]) \
        : "r"(addr))

__device__ __forceinline__ void mma_tf32_ss(uint32_t d, uint64_t ad, uint64_t bd,
                                            uint32_t idesc, bool acc) {
    uint32_t en = acc ? 1u : 0u, z = 0u;
    asm volatile(
        "{\n\t.reg .pred p;\n\tsetp.ne.u32 p, %6, 0;\n\t"
        "tcgen05.mma.cta_group::1.kind::tf32 [%0], %1, %2, %3, {%4, %4, %4, %4}, p;\n\t}"
        :: "r"(d), "l"(ad), "l"(bd), "r"(idesc), "r"(z), "r"(z), "r"(en) : "memory");
}
#endif  // HAS_TCGEN05

// ---------------- weight packing (SIMT fallback pass only needs these) --------
__global__ void pack_weights_k(const float* __restrict__ wl, const float* __restrict__ ul,
                               const float* __restrict__ wr, const float* __restrict__ ur) {
    int idx = blockIdx.x * blockDim.x + threadIdx.x;
    if (idx >= KD * JD) return;
    int k = idx / JD, j = idx % JD;
    g_wlt[idx] = (j < 1536) ? wl[(size_t)j * KD + k] : ul[(size_t)(j - 1536) * KD + k];
    g_wrt[idx] = (j < 1536) ? wr[(size_t)j * KD + k] : ur[(size_t)(j - 1536) * KD + k];
}

// ---------------- level decomposition ----------------------------------------
__global__ void build_levels_k(const int* __restrict__ parent) {
    int tid = threadIdx.x;
    if (tid < NNODE) { g_count[tid] = 0; g_cursor[tid] = 0; g_icount[tid] = 0; g_icursor[tid] = 0; }
    if (tid == 0) g_nlev = 0;
    __syncthreads();
    if (tid < BB) {
        int base = tid * NNODE;
        for (int t = 0; t < NNODE; t++) g_haschild[base + t] = 0;
    }
    __syncthreads();
    if (tid < BB) {
        int base = tid * NNODE;
        g_lvl[base] = 0;
        atomicAdd(&g_count[0], 1);
        int mx = 0;
        for (int t = 1; t < NNODE; t++) {
            int p = parent[base + t];          // guaranteed p < t
            int L = (int)g_lvl[base + p] + 1;
            g_lvl[base + t] = (unsigned short)L;
            atomicAdd(&g_count[L], 1);
            g_haschild[base + p] = 1;
            if (L > mx) mx = L;
        }
        atomicMax(&g_nlev, mx + 1);
    }
    __syncthreads();
    if (tid < BB) {
        int base = tid * NNODE;
        for (int t = 0; t < NNODE; t++)
            if (g_haschild[base + t]) atomicAdd(&g_icount[g_lvl[base + t]], 1);
    }
    __syncthreads();
    if (tid == 0) {
        int s = 0, si = 0;
        for (int l = 0; l < NNODE; l++) {
            g_off[l] = s;  s  += g_count[l];
            g_ioff[l] = si; si += g_icount[l];
        }
        g_off[NNODE] = s; g_ioff[NNODE] = si;
    }
    __syncthreads();
    if (tid < BB) {
        int base = tid * NNODE;
        for (int t = 0; t < NNODE; t++) {
            int L = g_lvl[base + t];
            int pos = g_off[L] + atomicAdd(&g_cursor[L], 1);
            g_nodeid[pos] = (unsigned)(base + t);
            g_parid[pos]  = (t == 0) ? -1 : (base + parent[base + t]);
            if (g_haschild[base + t]) {
                int ip = g_ioff[L] + atomicAdd(&g_icursor[L], 1);
                g_iwork[ip] = base + t;
            }
        }
    }
}

// ---------------- SIMT GEMM tile (fallback pass only) -------------------------
#if !HAS_TCGEN05
template<bool GATHER, int NT>
__device__ __forceinline__ void gemm_tile(
    const float* Asrc, const int* rows, int M,
    const float* __restrict__ Bt, float* Cout, const int* outrows, int tm, int tn) {
    __shared__ float As[BKT][BM + 4];
    __shared__ float Bs[BKT][BN];
    int tid = threadIdx.x;
    if (tid >= 256) { for (int k0 = 0; k0 < KD; k0 += BKT) { __syncthreads(); __syncthreads(); } return; }
    int tx = tid & 15, ty = tid >> 4;
    int row0 = tm * BM, col0 = tn * BN;

    float acc[4][8];
#pragma unroll
    for (int m = 0; m < 4; m++)
#pragma unroll
        for (int n = 0; n < 8; n++) acc[m][n] = 0.f;

    int arow = tid >> 2;
    int akq  = (tid & 3) * 4;
    const float* aptr = nullptr;
    {
        int r = row0 + arow;
        if (GATHER) {
            int p = (r < M) ? rows[r] : -1;
            if (p >= 0) aptr = Asrc + (size_t)p * KD;
        } else {
            if (r < M) aptr = Asrc + (size_t)r * KD;
        }
    }

    for (int k0 = 0; k0 < KD; k0 += BKT) {
        float4 av = make_float4(0.f, 0.f, 0.f, 0.f);
        if (aptr) av = *(const float4*)(aptr + k0 + akq);
        As[akq + 0][arow] = av.x;
        As[akq + 1][arow] = av.y;
        As[akq + 2][arow] = av.z;
        As[akq + 3][arow] = av.w;
#pragma unroll
        for (int i = 0; i < 2; i++) {
            int f  = tid + i * 256;
            int bk = f >> 5;
            int c4 = (f & 31) * 4;
            *(float4*)&Bs[bk][c4] = *(const float4*)(Bt + (size_t)(k0 + bk) * JD + col0 + c4);
        }
        __syncthreads();
#pragma unroll
        for (int k = 0; k < BKT; k++) {
            float a[4], b[8];
            *(float4*)a       = *(const float4*)&As[k][ty * 4];
            *(float4*)b       = *(const float4*)&Bs[k][tx * 8];
            *(float4*)(b + 4) = *(const float4*)&Bs[k][tx * 8 + 4];
#pragma unroll
            for (int m = 0; m < 4; m++)
#pragma unroll
                for (int n = 0; n < 8; n++) acc[m][n] = fmaf(a[m], b[n], acc[m][n]);
        }
        __syncthreads();
    }

#pragma unroll
    for (int m = 0; m < 4; m++) {
        int r = row0 + ty * 4 + m;
        if (r < M) {
            int orow = outrows ? outrows[r] : r;
            float* cp = Cout + (size_t)orow * JD + col0 + tx * 8;
            *(float4*)cp       = make_float4(acc[m][0], acc[m][1], acc[m][2], acc[m][3]);
            *(float4*)(cp + 4) = make_float4(acc[m][4], acc[m][5], acc[m][6], acc[m][7]);
        }
    }
}
#endif

// ---------------- LEFT projection GEMM ----------------------------------------
// out[node, j] = sum_k emb[node,k] * W[j,k], W rows = wl (j<1536) / ul (j>=1536).
// Double-buffered: load chunk c+1 while MMA of chunk c runs (2 mbars, 1/buffer).
__global__ __launch_bounds__(256, 2) void left_tc_k(const float* __restrict__ emb,
                                                    const float* __restrict__ wl,
                                                    const float* __restrict__ ul) {
#if HAS_TCGEN05
    extern __shared__ char dynbuf[];
    __shared__ uint32_t s_tmem;
    __shared__ __align__(8) unsigned long long s_mbar[2];

    int tid = threadIdx.x;
    int wid = tid >> 5, lane = tid & 31;
    int row0 = blockIdx.y * LTM;      // node rows
    int col0 = blockIdx.x * LTN;      // j cols

    uint32_t raw = smem_u32(dynbuf);
    uint32_t base0 = (raw + 1023u) & ~1023u;
    uint32_t aB0 = base0,              bB0 = base0 + TILEB;
    uint32_t aB1 = base0 + 2 * TILEB,  bB1 = base0 + 3 * TILEB;
    char* aP0 = dynbuf + (aB0 - raw); char* bP0 = dynbuf + (bB0 - raw);
    char* aP1 = dynbuf + (aB1 - raw); char* bP1 = dynbuf + (bB1 - raw);
    uint32_t mb0 = smem_u32(&s_mbar[0]), mb1 = smem_u32(&s_mbar[1]);
    uint32_t tp = smem_u32(&s_tmem);

    if (wid == 0) { TCGEN05_ALLOC(tp, 128); TCGEN05_RELINQ(); }
    if (tid == 0) { MBARRIER_INIT(mb0, 1); MBARRIER_INIT(mb1, 1); }
    __syncthreads();
    uint32_t tmem;
    asm volatile("ld.shared.b32 %0, [%1];" : "=r"(tmem) : "r"(tp));

    uint64_t ad0 = MAKE_SMEM_DESC(aB0), bd0 = MAKE_SMEM_DESC(bB0);
    uint64_t ad1 = MAKE_SMEM_DESC(aB1), bd1 = MAKE_SMEM_DESC(bB1);

    auto load_chunk = [&](int c, char* aPtr, char* bPtr) {
        int kc0 = c * LKC;
#pragma unroll
        for (int i = 0; i < 4; i++) {
            int f = tid + (i << 8);
            int row = f >> 3, seg = f & 7;
            float4 v = *(const float4*)(emb + (size_t)(row0 + row) * KD + kc0 + seg * 4);
            uint4 t = make_uint4(to_tf32(v.x), to_tf32(v.y), to_tf32(v.z), to_tf32(v.w));
            *(uint4*)(aPtr + SMEM_SWIZZLE_128B(row * 128 + seg * 16)) = t;
        }
#pragma unroll
        for (int i = 0; i < 4; i++) {
            int f = tid + (i << 8);
            int row = f >> 3, seg = f & 7;
            int j = col0 + row;
            const float* src = (j < 1536) ? (wl + (size_t)j * KD) : (ul + (size_t)(j - 1536) * KD);
            float4 v = *(const float4*)(src + kc0 + seg * 4);
            uint4 t = make_uint4(to_tf32(v.x), to_tf32(v.y), to_tf32(v.z), to_tf32(v.w));
            *(uint4*)(bPtr + SMEM_SWIZZLE_128B(row * 128 + seg * 16)) = t;
        }
    };

    for (int cp = 0; cp < LCHUNKS / 2; cp++) {
        // even chunk on buffer 0
        if (cp > 0) MBARRIER_WAIT_PARITY(mb0, (cp - 1) & 1);
        load_chunk(2 * cp, aP0, bP0);
        __syncthreads();
        FENCE_PROXY_ASYNC();
        if (wid == 0 && elect_one_pred()) {
#pragma unroll
            for (int s = 0; s < 4; s++)
                mma_tf32_ss(tmem, ad0 + s * 2, bd0 + s * 2, LIDESC, (cp > 0) || (s > 0));
            TCGEN05_COMMIT(mb0);
        }
        // odd chunk on buffer 1
        if (cp > 0) MBARRIER_WAIT_PARITY(mb1, (cp - 1) & 1);
        load_chunk(2 * cp + 1, aP1, bP1);
        __syncthreads();
        FENCE_PROXY_ASYNC();
        if (wid == 0 && elect_one_pred()) {
#pragma unroll
            for (int s = 0; s < 4; s++)
                mma_tf32_ss(tmem, ad1 + s * 2, bd1 + s * 2, LIDESC, true);
            TCGEN05_COMMIT(mb1);
        }
    }
    // last commit (mb1, count LCHUNKS/2) covers ALL prior MMAs
    MBARRIER_WAIT_PARITY(mb1, (LCHUNKS / 2 - 1) & 1);
    TCGEN05_FENCE_AFTER();

    if (wid < 4) {
        int r = row0 + wid * 32 + lane;
        float* dst0 = g_left + (size_t)r * JD + col0;
#pragma unroll
        for (int cb = 0; cb < LTN; cb += 32) {
            uint32_t d[32];
            TCGEN05_LD_32X32B_X32(d, tmem + cb);
            TCGEN05_WAIT_LD();
            float4* dst4 = (float4*)(dst0 + cb);
#pragma unroll
            for (int q = 0; q < 8; q++)
                dst4[q] = make_float4(__uint_as_float(d[4 * q]), __uint_as_float(d[4 * q + 1]),
                                      __uint_as_float(d[4 * q + 2]), __uint_as_float(d[4 * q + 3]));
        }
        TCGEN05_FENCE_BEFORE();
    }
    __syncthreads();
    if (wid == 0) TCGEN05_DEALLOC(tmem, 128);
#else
    for (int half = 0; half < 2; half++) {
        int rowbase = blockIdx.y * LTM + half * BM;
        gemm_tile<false, 256>(emb + (size_t)rowbase * KD, nullptr, BM, g_wlt,
                              g_left + (size_t)rowbase * JD, nullptr, 0, blockIdx.x);
        __syncthreads();
    }
#endif
}

// ---------------- grid barrier ----------------------------------------------
__device__ __forceinline__ void grid_barrier(unsigned target) {
    __syncthreads();
    if (threadIdx.x == 0) {
        __threadfence();
        unsigned arrived = atomicAdd(&g_bar_count, 1);
        if (arrived == gridDim.x - 1) {
            atomicExch(&g_bar_count, 0);
            __threadfence();
            atomicExch(&g_bar_epoch, target);
        } else {
            unsigned cur;
            do {
                asm volatile("ld.acquire.gpu.u32 %0, [%1];" : "=r"(cur) : "l"(&g_bar_epoch));
                if (cur >= target) break;
                __nanosleep(64);
            } while (true);
        }
    }
    __syncthreads();
}

// ---------------- persistent level-sweep kernel -------------------------------
// Per level L: (A) epilogue for all L-nodes (reads g_rw[parent], computed when the
// parent's level ran phase B); (B) right-GEMM (tcgen05 tf32, double-buffered) for
// INTERNAL L-nodes only: g_rw[nid] = h[nid] @ Wright^T (dedup: one row/parent).
__global__ __launch_bounds__(TLB) void tree_lstm_k(float* hout,
                                                   const float* __restrict__ wo,
                                                   const float* __restrict__ bias,
                                                   const float* __restrict__ wr,
                                                   const float* __restrict__ ur) {
    __shared__ float pooled_s[TLB / 32][24];
    unsigned epoch = g_bar_epoch;   // carries across graph replays; uniform at entry
    int nlev = g_nlev;
    int tid  = threadIdx.x;
    int warp = tid >> 5, lane = tid & 31;
    int gw = blockIdx.x * (TLB / 32) + warp;
    int nw = gridDim.x * (TLB / 32);

#if HAS_TCGEN05
    extern __shared__ char dynbuf[];
    __shared__ int s_idx[LTM];
    __shared__ uint32_t s_tmem;
    __shared__ __align__(8) unsigned long long s_mbar[2];
    uint32_t raw = smem_u32(dynbuf);
    uint32_t base0 = (raw + 1023u) & ~1023u;
    uint32_t aB0 = base0,              bB0 = base0 + TILEB;
    uint32_t aB1 = base0 + 2 * TILEB,  bB1 = base0 + 3 * TILEB;
    char* aP0 = dynbuf + (aB0 - raw); char* bP0 = dynbuf + (bB0 - raw);
    char* aP1 = dynbuf + (aB1 - raw); char* bP1 = dynbuf + (bB1 - raw);
    uint32_t mb0 = smem_u32(&s_mbar[0]), mb1 = smem_u32(&s_mbar[1]);
    uint32_t tp = smem_u32(&s_tmem);
    if (warp == 0) { TCGEN05_ALLOC(tp, 128); TCGEN05_RELINQ(); }
    if (tid == 0) { MBARRIER_INIT(mb0, 1); MBARRIER_INIT(mb1, 1); }
    __syncthreads();
    uint32_t tmem;
    asm volatile("ld.shared.b32 %0, [%1];" : "=r"(tmem) : "r"(tp));
    uint64_t ad0 = MAKE_SMEM_DESC(aB0), bd0 = MAKE_SMEM_DESC(bB0);
    uint64_t ad1 = MAKE_SMEM_DESC(aB1), bd1 = MAKE_SMEM_DESC(bB1);
    int cnt0 = 0, cnt1 = 0;    // commits issued per mbar (uniform across threads)
#endif

    for (int lvl = 0; lvl < nlev; lvl++) {
        int base = g_off[lvl];
        int M    = g_off[lvl + 1] - base;

        // ---------------- Phase A: per-node epilogue (warp per node) ----------
        for (int i = gw; i < M; i += nw) {
            unsigned nid = g_nodeid[base + i];
            int pidx = g_parid[base + i];
            const float* Lrow = g_left + (size_t)nid * JD;

            if (pidx >= 0) {
                const float* Rrow = g_rw + (size_t)pidx * JD;
                // pooled[g,p] = sum_r lw*rw — 4 independent butterfly chains for ILP
#pragma unroll
                for (int gq = 0; gq < 24; gq += 4) {
                    float v0, v1, v2, v3;
                    { int o = (gq + 0) * 64 + lane; v0 = Lrow[o] * Rrow[o] + Lrow[o + 32] * Rrow[o + 32]; }
                    { int o = (gq + 1) * 64 + lane; v1 = Lrow[o] * Rrow[o] + Lrow[o + 32] * Rrow[o + 32]; }
                    { int o = (gq + 2) * 64 + lane; v2 = Lrow[o] * Rrow[o] + Lrow[o + 32] * Rrow[o + 32]; }
                    { int o = (gq + 3) * 64 + lane; v3 = Lrow[o] * Rrow[o] + Lrow[o + 32] * Rrow[o + 32]; }
#pragma unroll
                    for (int s = 16; s > 0; s >>= 1) {
                        v0 += __shfl_xor_sync(0xffffffffu, v0, s);
                        v1 += __shfl_xor_sync(0xffffffffu, v1, s);
                        v2 += __shfl_xor_sync(0xffffffffu, v2, s);
                        v3 += __shfl_xor_sync(0xffffffffu, v3, s);
                    }
                    if (lane == 0) {
                        pooled_s[warp][gq + 0] = v0;
                        pooled_s[warp][gq + 1] = v1;
                        pooled_s[warp][gq + 2] = v2;
                        pooled_s[warp][gq + 3] = v3;
                    }
                }
                __syncwarp();
                for (int hh = lane; hh < HD; hh += 32) {
                    float gv[3];
#pragma unroll
                    for (int g = 0; g < 3; g++) {
                        float acc = bias[g * HD + hh] + Lrow[1536 + g * HD + hh]
                                  + Rrow[1536 + g * HD + hh];
                        const float* wop = wo + (size_t)(g * HD + hh) * 8;
#pragma unroll
                        for (int p = 0; p < 8; p++) acc = fmaf(pooled_s[warp][g * 8 + p], wop[p], acc);
                        gv[g] = acc;
                    }
                    float f  = 1.f / (1.f + expf(-gv[0]));
                    float o_ = 1.f / (1.f + expf(-gv[1]));
                    float z  = tanhf(gv[2]);
                    float pc = g_c[(size_t)pidx * HD + hh];
                    float c  = pc * f + (1.f - f) * z;
                    float h  = o_ * tanhf(c);
                    g_c[(size_t)nid * HD + hh]  = c;
                    hout[(size_t)nid * HD + hh] = h;
                }
                __syncwarp();   // pooled_s reuse
            } else {
                // root: parent h == 0 -> pooled = 0, right-linear = 0, pc = 0
                for (int hh = lane; hh < HD; hh += 32) {
                    float gv[3];
#pragma unroll
                    for (int g = 0; g < 3; g++)
                        gv[g] = bias[g * HD + hh] + Lrow[1536 + g * HD + hh];
                    float f  = 1.f / (1.f + expf(-gv[0]));
                    float o_ = 1.f / (1.f + expf(-gv[1]));
                    float z  = tanhf(gv[2]);
                    float c  = (1.f - f) * z;
                    float h  = o_ * tanhf(c);
                    g_c[(size_t)nid * HD + hh]  = c;
                    hout[(size_t)nid * HD + hh] = h;
                }
            }
        }
        epoch++; grid_barrier(epoch);

        // ---------------- Phase B: right-GEMM for internal nodes --------------
        int ibase = g_ioff[lvl];
        int Mi    = g_ioff[lvl + 1] - ibase;
        if (Mi > 0) {
#if HAS_TCGEN05
            int ntm = (Mi + LTM - 1) / LTM;
            int ntiles = ntm * NTN;
            for (int tile = blockIdx.x; tile < ntiles; tile += gridDim.x) {
                int tm = tile / NTN, tn = tile % NTN;
                int row0 = tm * LTM, col0 = tn * LTN;

                // cache gather indices for this tile
                if (tid < LTM) {
                    int r = row0 + tid;
                    s_idx[tid] = (r < Mi) ? g_iwork[ibase + r] : -1;
                }
                __syncthreads();

                auto load_chunk = [&](int c, char* aPtr, char* bPtr) {
                    int kc0 = c * LKC;
#pragma unroll
                    for (int i = 0; i < 2; i++) {
                        int f = tid + (i << 9);
                        int row = f >> 3, seg = f & 7;
                        int src_r = s_idx[row];
                        float4 v = make_float4(0.f, 0.f, 0.f, 0.f);
                        if (src_r >= 0)
                            v = *(const float4*)(hout + (size_t)src_r * KD + kc0 + seg * 4);
                        uint4 t = make_uint4(to_tf32(v.x), to_tf32(v.y), to_tf32(v.z), to_tf32(v.w));
                        *(uint4*)(aPtr + SMEM_SWIZZLE_128B(row * 128 + seg * 16)) = t;
                    }
#pragma unroll
                    for (int i = 0; i < 2; i++) {
                        int f = tid + (i << 9);
                        int row = f >> 3, seg = f & 7;
                        int j = col0 + row;
                        const float* src = (j < 1536) ? (wr + (size_t)j * KD)
                                                      : (ur + (size_t)(j - 1536) * KD);
                        float4 v = *(const float4*)(src + kc0 + seg * 4);
                        uint4 t = make_uint4(to_tf32(v.x), to_tf32(v.y), to_tf32(v.z), to_tf32(v.w));
                        *(uint4*)(bPtr + SMEM_SWIZZLE_128B(row * 128 + seg * 16)) = t;
                    }
                };

                for (int cp = 0; cp < LCHUNKS / 2; cp++) {
                    // even chunk -> buffer 0
                    if (cnt0 > 0) MBARRIER_WAIT_PARITY(mb0, (cnt0 - 1) & 1);
                    load_chunk(2 * cp, aP0, bP0);
                    __syncthreads();
                    FENCE_PROXY_ASYNC();
                    if (warp == 0 && elect_one_pred()) {
#pragma unroll
                        for (int s = 0; s < 4; s++)
                            mma_tf32_ss(tmem, ad0 + s * 2, bd0 + s * 2, LIDESC, (cp > 0) || (s > 0));
                        TCGEN05_COMMIT(mb0);
                    }
                    cnt0++;
                    // odd chunk -> buffer 1
                    if (cnt1 > 0) MBARRIER_WAIT_PARITY(mb1, (cnt1 - 1) & 1);
                    load_chunk(2 * cp + 1, aP1, bP1);
                    __syncthreads();
                    FENCE_PROXY_ASYNC();
                    if (warp == 0 && elect_one_pred()) {
#pragma unroll
                        for (int s = 0; s < 4; s++)
                            mma_tf32_ss(tmem, ad1 + s * 2, bd1 + s * 2, LIDESC, true);
                        TCGEN05_COMMIT(mb1);
                    }
                    cnt1++;
                }
                // last commit (mb1) covers all prior MMAs of this tile
                MBARRIER_WAIT_PARITY(mb1, (cnt1 - 1) & 1);
                TCGEN05_FENCE_AFTER();
                if (warp < 4) {
                    int row = warp * 32 + lane;
                    int dst_r = s_idx[row];
                    float* dst0 = (dst_r >= 0) ? (g_rw + (size_t)dst_r * JD + col0) : nullptr;
#pragma unroll
                    for (int cb = 0; cb < LTN; cb += 32) {
                        uint32_t d[32];
                        TCGEN05_LD_32X32B_X32(d, tmem + cb);
                        TCGEN05_WAIT_LD();
                        if (dst0) {
                            float4* dst4 = (float4*)(dst0 + cb);
#pragma unroll
                            for (int q = 0; q < 8; q++)
                                dst4[q] = make_float4(__uint_as_float(d[4 * q]),
                                                      __uint_as_float(d[4 * q + 1]),
                                                      __uint_as_float(d[4 * q + 2]),
                                                      __uint_as_float(d[4 * q + 3]));
                        }
                    }
                    TCGEN05_FENCE_BEFORE();
                }
                __syncthreads();   // TMEM reads + s_idx uses done before next tile
            }
#else
            int ntiles = ((Mi + BM - 1) / BM) * (JD / BN);
            for (int tile = blockIdx.x; tile < ntiles; tile += gridDim.x) {
                gemm_tile<true, TLB>(hout, g_iwork + ibase, Mi, g_wrt,
                                     g_rw, g_iwork + ibase, tile / (JD / BN), tile % (JD / BN));
            }
#endif
        }
        epoch++; grid_barrier(epoch);
    }
#if HAS_TCGEN05
    __syncthreads();
    if (warp == 0) TCGEN05_DEALLOC(tmem, 128);
#endif
}

// ---------------- launch ------------------------------------------------------
extern "C" void kernel_launch(void* const* d_in, const int* in_sizes, int n_in,
                              void* d_out, int out_size) {
    const float* emb    = (const float*)d_in[0];
    const int*   parent = (const int*)d_in[1];
    // d_in[2] = node_mask (unused, all ones)
    const float* wl   = (const float*)d_in[3];
    const float* wr   = (const float*)d_in[4];
    const float* wo   = (const float*)d_in[5];
    const float* ul   = (const float*)d_in[6];
    const float* ur   = (const float*)d_in[7];
    const float* bias = (const float*)d_in[8];
    float* hout = (float*)d_out;

    static int attr_done = 0;
    if (!attr_done) {
        cudaFuncSetAttribute(left_tc_k, cudaFuncAttributeMaxDynamicSharedMemorySize, DSMEM_BYTES);
        cudaFuncSetAttribute(tree_lstm_k, cudaFuncAttributeMaxDynamicSharedMemorySize, DSMEM_BYTES);
        attr_done = 1;
    }

    pack_weights_k<<<(KD * JD + 255) / 256, 256>>>(wl, ul, wr, ur);
    build_levels_k<<<1, 512>>>(parent);
    left_tc_k<<<dim3(JD / LTN, NTOT / LTM), 256, DSMEM_BYTES>>>(emb, wl, ul);
    tree_lstm_k<<<NCTA, TLB, DSMEM_BYTES>>>(hout, wo, bias, wr, ur);
}

// round 15
// speedup vs baseline: 1.6265x; 1.6265x over previous
#include <cuda_runtime.h>
#include <cstdint>

// Problem constants
#define BB     128
#define NNODE  512
#define KD     512          // IN == HID == 512 (contraction dim)
#define HD     512
#define JD     3072         // 1536 bilinear (g,p,r) + 1536 linear (g,h)
#define NTOT   (BB * NNODE) // 65536 nodes

// SIMT GEMM tile config (fallback pass only)
#define BM     64
#define BN     128
#define BKT    16

// Persistent kernel shape
#define NCTA   148
#define TLB    512          // threads per block in tree_lstm (16 warps)

// Tensor-core GEMM tile (tf32)
#define LTM    128
#define LTN    128
#define LKC    32                 // K elements per chunk = 128 bytes (tf32)
#define LCHUNKS (KD / LKC)        // 16
#define NTN    (JD / LTN)         // 24 column tiles
#define TILEB  16384              // one 128x128B SMEM tile
#define WOT_FLOATS (3 * HD * 8)   // transposed wo: [p][g*HD+h]
#define WOT_BYTES  (WOT_FLOATS * 4)
#define DSMEM_LEFT (4 * TILEB + 1024)
#define DSMEM_TREE (4 * TILEB + WOT_BYTES + 1024)
// idesc: dtype F32=1 @bit4, atype TF32=2 @bit7, btype TF32=2 @bit10, N/8 @bit17, M/16 @bit24
#define LIDESC ((1u << 4) | (2u << 7) | (2u << 10) | ((LTN / 8u) << 17) | ((LTM / 16u) << 24))

// tcgen05 is only legal in the arch-SPECIFIC (sm_103a) compilation pass. The
// harness also runs a plain compute_103 ptxas pass, which rejects tcgen05
// outright — so every tcgen05 token must vanish from that pass.
#if defined(__CUDA_ARCH_FEAT_SM103_ALL) || defined(__CUDA_ARCH_FEAT_SM100_ALL) || \
    (defined(__CUDA_ARCH_SPECIFIC__) && (__CUDA_ARCH_SPECIFIC__ == 1030))
#define HAS_TCGEN05 1
#else
#define HAS_TCGEN05 0
#endif

// ---------------- device globals (no runtime allocation allowed) -------------
__device__ float g_left[(size_t)NTOT * JD];   // left projections, by node id
__device__ float g_rw[(size_t)NTOT * JD];     // right projections, BY NODE ID (dedup)
__device__ float g_c[(size_t)NTOT * HD];      // cell state, by node id
__device__ float g_wlt[KD * JD];              // Wleft  transposed [k][j] (SIMT fallback)
__device__ float g_wrt[KD * JD];              // Wright transposed [k][j] (SIMT fallback)
__device__ float g_wot[WOT_FLOATS];           // wo transposed: [p][g*HD+h]
__device__ unsigned short g_lvl[NTOT];
__device__ unsigned char g_haschild[NTOT];
__device__ int g_count[NNODE];
__device__ int g_off[NNODE + 1];
__device__ int g_cursor[NNODE];
__device__ int g_icount[NNODE];
__device__ int g_ioff[NNODE + 1];
__device__ int g_icursor[NNODE];
__device__ int g_nlev;
__device__ unsigned g_nodeid[NTOT];           // worklist: flat node id b*N+t
__device__ int g_parid[NTOT];                 // worklist: flat parent id, -1 = root
__device__ int g_iwork[NTOT];                 // internal-node worklist (by level)
__device__ unsigned g_bar_count;              // grid barrier (self-resetting)
__device__ unsigned g_bar_epoch;              // monotonic across replays

// ---------------- generic helpers (legal on all passes) -----------------------
__device__ __forceinline__ uint32_t smem_u32(const void* p) {
    uint32_t a;
    asm("{ .reg .u64 t; cvta.to.shared.u64 t, %1; cvt.u32.u64 %0, t; }" : "=r"(a) : "l"(p));
    return a;
}
#define SMEM_SWIZZLE_128B(o) ((o) ^ (((o) >> 3) & 0x70))

// Fast activations: __expf-based, sign-safe; ~1e-6 rel err (noise vs tf32 4.5e-4)
__device__ __forceinline__ float fsigmoid(float x) { return 1.f / (1.f + __expf(-x)); }
__device__ __forceinline__ float ftanh(float x) {
    float t = __expf(-2.f * fabsf(x));
    return copysignf((1.f - t) / (1.f + t), x);
}

#if HAS_TCGEN05
__device__ __forceinline__ uint32_t elect_one_pred() {
    uint32_t p;
    asm volatile("{ .reg .pred p; elect.sync _|p, 0xFFFFFFFF; selp.b32 %0, 1, 0, p; }" : "=r"(p));
    return p;
}
__device__ __forceinline__ uint32_t to_tf32(float x) {
    uint32_t r; asm("cvt.rna.tf32.f32 %0, %1;" : "=r"(r) : "f"(x)); return r;
}

static constexpr uint64_t SMEM_DESC_BASE_SW128 =
    (uint64_t(2) << 61) | (uint64_t(1) << 46) | (uint64_t(64) << 32) | (uint64_t(1) << 16);
#define MAKE_SMEM_DESC(base) (SMEM_DESC_BASE_SW128 | ((uint64_t)((base) >> 4) & 0x3FFF))

#define TCGEN05_ALLOC(sres, n) \
    asm volatile("tcgen05.alloc.cta_group::1.sync.aligned.shared::cta.b32 [%0], %1;" \
                 :: "r"((uint32_t)(sres)), "r"((uint32_t)(n)) : "memory")
#define TCGEN05_DEALLOC(t, n) \
    asm volatile("tcgen05.dealloc.cta_group::1.sync.aligned.b32 %0, %1;" :: "r"(t), "r"((uint32_t)(n)))
#define TCGEN05_RELINQ() \
    asm volatile("tcgen05.relinquish_alloc_permit.cta_group::1.sync.aligned;")
#define TCGEN05_COMMIT(mb) \
    asm volatile("tcgen05.commit.cta_group::1.mbarrier::arrive::one.shared::cluster.b64 [%0];" \
                 :: "r"((uint32_t)(mb)) : "memory")
#define TCGEN05_FENCE_AFTER()  asm volatile("tcgen05.fence::after_thread_sync;" ::: "memory")
#define TCGEN05_FENCE_BEFORE() asm volatile("tcgen05.fence::before_thread_sync;" ::: "memory")
#define TCGEN05_WAIT_LD()      asm volatile("tcgen05.wait::ld.sync.aligned;" ::: "memory")
#define FENCE_PROXY_ASYNC()    asm volatile("fence.proxy.async.shared::cta;" ::: "memory")
#define MBARRIER_INIT(mb, c) \
    asm volatile("mbarrier.init.shared.b64 [%0], %1;" :: "r"((uint32_t)(mb)), "r"((uint32_t)(c)) : "memory")
#define MBARRIER_WAIT_PARITY(mb, ph) do { \
    uint32_t _m = (uint32_t)(mb), _p = (uint32_t)(ph), _d; \
    asm volatile("{ .reg .pred p; mbarrier.try_wait.parity.acquire.cta.shared::cta.b64 p, [%1], %2; selp.b32 %0, 1, 0, p; }" \
                 : "=r"(_d) : "r"(_m), "r"(_p) : "memory"); \
    if (!_d) { \
        asm volatile("{ .reg .pred P1; WL_%=: mbarrier.try_wait.parity.acquire.cta.shared::cta.b64 P1, [%0], %1, 0x989680; @P1 bra.uni WD_%=; bra.uni WL_%=; WD_%=: }" \
                     :: "r"(_m), "r"(_p) : "memory"); \
    } } while (0)

#define TCGEN05_LD_32X32B_X32(r, addr) \
    asm volatile("tcgen05.ld.sync.aligned.32x32b.x32.b32 " \
        "{%0, %1, %2, %3, %4, %5, %6, %7, %8, %9, %10, %11, %12, %13, %14, %15, " \
        " %16, %17, %18, %19, %20, %21, %22, %23, %24, %25, %26, %27, %28, %29, %30, %31}, [%32];" \
        : "=r"((r)[0]),  "=r"((r)[1]),  "=r"((r)[2]),  "=r"((r)[3]), \
          "=r"((r)[4]),  "=r"((r)[5]),  "=r"((r)[6]),  "=r"((r)[7]), \
          "=r"((r)[8]),  "=r"((r)[9]),  "=r"((r)[10]), "=r"((r)[11]), \
          "=r"((r)[12]), "=r"((r)[13]), "=r"((r)[14]), "=r"((r)[15]), \
          "=r"((r)[16]), "=r"((r)[17]), "=r"((r)[18]), "=r"((r)[19]), \
          "=r"((r)[20]), "=r"((r)[21]), "=r"((r)[22]), "=r"((r)[23]), \
          "=r"((r)[24]), "=r"((r)[25]), "=r"((r)[26]), "=r"((r)[27]), \
          "=r"((r)[28]), "=r"((r)[29]), "=r"((r)[30]), "=r"((r)[31]) \
        : "r"(addr))

__device__ __forceinline__ void mma_tf32_ss(uint32_t d, uint64_t ad, uint64_t bd,
                                            uint32_t idesc, bool acc) {
    uint32_t en = acc ? 1u : 0u, z = 0u;
    asm volatile(
        "{\n\t.reg .pred p;\n\tsetp.ne.u32 p, %6, 0;\n\t"
        "tcgen05.mma.cta_group::1.kind::tf32 [%0], %1, %2, %3, {%4, %4, %4, %4}, p;\n\t}"
        :: "r"(d), "l"(ad), "l"(bd), "r"(idesc), "r"(z), "r"(z), "r"(en) : "memory");
}
#endif  // HAS_TCGEN05

// ---------------- weight packing ----------------------------------------------
__global__ void pack_weights_k(const float* __restrict__ wl, const float* __restrict__ ul,
                               const float* __restrict__ wr, const float* __restrict__ ur,
                               const float* __restrict__ wo) {
    int idx = blockIdx.x * blockDim.x + threadIdx.x;
    if (idx < WOT_FLOATS) {
        int gh = idx >> 3, p = idx & 7;      // wo shape (3, HID, POOL) row-major
        g_wot[p * (3 * HD) + gh] = wo[idx];
    }
    if (idx >= KD * JD) return;
    int k = idx / JD, j = idx % JD;
    g_wlt[idx] = (j < 1536) ? wl[(size_t)j * KD + k] : ul[(size_t)(j - 1536) * KD + k];
    g_wrt[idx] = (j < 1536) ? wr[(size_t)j * KD + k] : ur[(size_t)(j - 1536) * KD + k];
}

// ---------------- level decomposition ----------------------------------------
__global__ void build_levels_k(const int* __restrict__ parent) {
    int tid = threadIdx.x;
    if (tid < NNODE) { g_count[tid] = 0; g_cursor[tid] = 0; g_icount[tid] = 0; g_icursor[tid] = 0; }
    if (tid == 0) g_nlev = 0;
    __syncthreads();
    if (tid < BB) {
        int base = tid * NNODE;
        for (int t = 0; t < NNODE; t++) g_haschild[base + t] = 0;
    }
    __syncthreads();
    if (tid < BB) {
        int base = tid * NNODE;
        g_lvl[base] = 0;
        atomicAdd(&g_count[0], 1);
        int mx = 0;
        for (int t = 1; t < NNODE; t++) {
            int p = parent[base + t];          // guaranteed p < t
            int L = (int)g_lvl[base + p] + 1;
            g_lvl[base + t] = (unsigned short)L;
            atomicAdd(&g_count[L], 1);
            g_haschild[base + p] = 1;
            if (L > mx) mx = L;
        }
        atomicMax(&g_nlev, mx + 1);
    }
    __syncthreads();
    if (tid < BB) {
        int base = tid * NNODE;
        for (int t = 0; t < NNODE; t++)
            if (g_haschild[base + t]) atomicAdd(&g_icount[g_lvl[base + t]], 1);
    }
    __syncthreads();
    if (tid == 0) {
        int s = 0, si = 0;
        for (int l = 0; l < NNODE; l++) {
            g_off[l] = s;  s  += g_count[l];
            g_ioff[l] = si; si += g_icount[l];
        }
        g_off[NNODE] = s; g_ioff[NNODE] = si;
    }
    __syncthreads();
    if (tid < BB) {
        int base = tid * NNODE;
        for (int t = 0; t < NNODE; t++) {
            int L = g_lvl[base + t];
            int pos = g_off[L] + atomicAdd(&g_cursor[L], 1);
            g_nodeid[pos] = (unsigned)(base + t);
            g_parid[pos]  = (t == 0) ? -1 : (base + parent[base + t]);
            if (g_haschild[base + t]) {
                int ip = g_ioff[L] + atomicAdd(&g_icursor[L], 1);
                g_iwork[ip] = base + t;
            }
        }
    }
}

// ---------------- SIMT GEMM tile (fallback pass only) -------------------------
#if !HAS_TCGEN05
template<bool GATHER, int NT>
__device__ __forceinline__ void gemm_tile(
    const float* Asrc, const int* rows, int M,
    const float* __restrict__ Bt, float* Cout, const int* outrows, int tm, int tn) {
    __shared__ float As[BKT][BM + 4];
    __shared__ float Bs[BKT][BN];
    int tid = threadIdx.x;
    if (tid >= 256) { for (int k0 = 0; k0 < KD; k0 += BKT) { __syncthreads(); __syncthreads(); } return; }
    int tx = tid & 15, ty = tid >> 4;
    int row0 = tm * BM, col0 = tn * BN;

    float acc[4][8];
#pragma unroll
    for (int m = 0; m < 4; m++)
#pragma unroll
        for (int n = 0; n < 8; n++) acc[m][n] = 0.f;

    int arow = tid >> 2;
    int akq  = (tid & 3) * 4;
    const float* aptr = nullptr;
    {
        int r = row0 + arow;
        if (GATHER) {
            int p = (r < M) ? rows[r] : -1;
            if (p >= 0) aptr = Asrc + (size_t)p * KD;
        } else {
            if (r < M) aptr = Asrc + (size_t)r * KD;
        }
    }

    for (int k0 = 0; k0 < KD; k0 += BKT) {
        float4 av = make_float4(0.f, 0.f, 0.f, 0.f);
        if (aptr) av = *(const float4*)(aptr + k0 + akq);
        As[akq + 0][arow] = av.x;
        As[akq + 1][arow] = av.y;
        As[akq + 2][arow] = av.z;
        As[akq + 3][arow] = av.w;
#pragma unroll
        for (int i = 0; i < 2; i++) {
            int f  = tid + i * 256;
            int bk = f >> 5;
            int c4 = (f & 31) * 4;
            *(float4*)&Bs[bk][c4] = *(const float4*)(Bt + (size_t)(k0 + bk) * JD + col0 + c4);
        }
        __syncthreads();
#pragma unroll
        for (int k = 0; k < BKT; k++) {
            float a[4], b[8];
            *(float4*)a       = *(const float4*)&As[k][ty * 4];
            *(float4*)b       = *(const float4*)&Bs[k][tx * 8];
            *(float4*)(b + 4) = *(const float4*)&Bs[k][tx * 8 + 4];
#pragma unroll
            for (int m = 0; m < 4; m++)
#pragma unroll
                for (int n = 0; n < 8; n++) acc[m][n] = fmaf(a[m], b[n], acc[m][n]);
        }
        __syncthreads();
    }

#pragma unroll
    for (int m = 0; m < 4; m++) {
        int r = row0 + ty * 4 + m;
        if (r < M) {
            int orow = outrows ? outrows[r] : r;
            float* cp = Cout + (size_t)orow * JD + col0 + tx * 8;
            *(float4*)cp       = make_float4(acc[m][0], acc[m][1], acc[m][2], acc[m][3]);
            *(float4*)(cp + 4) = make_float4(acc[m][4], acc[m][5], acc[m][6], acc[m][7]);
        }
    }
}
#endif

// ---------------- LEFT projection GEMM ----------------------------------------
// out[node, j] = sum_k emb[node,k] * W[j,k], W rows = wl (j<1536) / ul (j>=1536).
// Double-buffered: load chunk c+1 while MMA of chunk c runs (2 mbars, 1/buffer).
__global__ __launch_bounds__(256, 2) void left_tc_k(const float* __restrict__ emb,
                                                    const float* __restrict__ wl,
                                                    const float* __restrict__ ul) {
#if HAS_TCGEN05
    extern __shared__ char dynbuf[];
    __shared__ uint32_t s_tmem;
    __shared__ __align__(8) unsigned long long s_mbar[2];

    int tid = threadIdx.x;
    int wid = tid >> 5, lane = tid & 31;
    int row0 = blockIdx.y * LTM;      // node rows
    int col0 = blockIdx.x * LTN;      // j cols

    uint32_t raw = smem_u32(dynbuf);
    uint32_t base0 = (raw + 1023u) & ~1023u;
    uint32_t aB0 = base0,              bB0 = base0 + TILEB;
    uint32_t aB1 = base0 + 2 * TILEB,  bB1 = base0 + 3 * TILEB;
    char* aP0 = dynbuf + (aB0 - raw); char* bP0 = dynbuf + (bB0 - raw);
    char* aP1 = dynbuf + (aB1 - raw); char* bP1 = dynbuf + (bB1 - raw);
    uint32_t mb0 = smem_u32(&s_mbar[0]), mb1 = smem_u32(&s_mbar[1]);
    uint32_t tp = smem_u32(&s_tmem);

    if (wid == 0) { TCGEN05_ALLOC(tp, 128); TCGEN05_RELINQ(); }
    if (tid == 0) { MBARRIER_INIT(mb0, 1); MBARRIER_INIT(mb1, 1); }
    __syncthreads();
    uint32_t tmem;
    asm volatile("ld.shared.b32 %0, [%1];" : "=r"(tmem) : "r"(tp));

    uint64_t ad0 = MAKE_SMEM_DESC(aB0), bd0 = MAKE_SMEM_DESC(bB0);
    uint64_t ad1 = MAKE_SMEM_DESC(aB1), bd1 = MAKE_SMEM_DESC(bB1);

    auto load_chunk = [&](int c, char* aPtr, char* bPtr) {
        int kc0 = c * LKC;
#pragma unroll
        for (int i = 0; i < 4; i++) {
            int f = tid + (i << 8);
            int row = f >> 3, seg = f & 7;
            float4 v = *(const float4*)(emb + (size_t)(row0 + row) * KD + kc0 + seg * 4);
            uint4 t = make_uint4(to_tf32(v.x), to_tf32(v.y), to_tf32(v.z), to_tf32(v.w));
            *(uint4*)(aPtr + SMEM_SWIZZLE_128B(row * 128 + seg * 16)) = t;
        }
#pragma unroll
        for (int i = 0; i < 4; i++) {
            int f = tid + (i << 8);
            int row = f >> 3, seg = f & 7;
            int j = col0 + row;
            const float* src = (j < 1536) ? (wl + (size_t)j * KD) : (ul + (size_t)(j - 1536) * KD);
            float4 v = *(const float4*)(src + kc0 + seg * 4);
            uint4 t = make_uint4(to_tf32(v.x), to_tf32(v.y), to_tf32(v.z), to_tf32(v.w));
            *(uint4*)(bPtr + SMEM_SWIZZLE_128B(row * 128 + seg * 16)) = t;
        }
    };

    for (int cp = 0; cp < LCHUNKS / 2; cp++) {
        // even chunk on buffer 0
        if (cp > 0) MBARRIER_WAIT_PARITY(mb0, (cp - 1) & 1);
        load_chunk(2 * cp, aP0, bP0);
        __syncthreads();
        FENCE_PROXY_ASYNC();
        if (wid == 0 && elect_one_pred()) {
#pragma unroll
            for (int s = 0; s < 4; s++)
                mma_tf32_ss(tmem, ad0 + s * 2, bd0 + s * 2, LIDESC, (cp > 0) || (s > 0));
            TCGEN05_COMMIT(mb0);
        }
        // odd chunk on buffer 1
        if (cp > 0) MBARRIER_WAIT_PARITY(mb1, (cp - 1) & 1);
        load_chunk(2 * cp + 1, aP1, bP1);
        __syncthreads();
        FENCE_PROXY_ASYNC();
        if (wid == 0 && elect_one_pred()) {
#pragma unroll
            for (int s = 0; s < 4; s++)
                mma_tf32_ss(tmem, ad1 + s * 2, bd1 + s * 2, LIDESC, true);
            TCGEN05_COMMIT(mb1);
        }
    }
    // last commit (mb1, count LCHUNKS/2) covers ALL prior MMAs
    MBARRIER_WAIT_PARITY(mb1, (LCHUNKS / 2 - 1) & 1);
    TCGEN05_FENCE_AFTER();

    if (wid < 4) {
        int r = row0 + wid * 32 + lane;
        float* dst0 = g_left + (size_t)r * JD + col0;
#pragma unroll
        for (int cb = 0; cb < LTN; cb += 32) {
            uint32_t d[32];
            TCGEN05_LD_32X32B_X32(d, tmem + cb);
            TCGEN05_WAIT_LD();
            float4* dst4 = (float4*)(dst0 + cb);
#pragma unroll
            for (int q = 0; q < 8; q++)
                dst4[q] = make_float4(__uint_as_float(d[4 * q]), __uint_as_float(d[4 * q + 1]),
                                      __uint_as_float(d[4 * q + 2]), __uint_as_float(d[4 * q + 3]));
        }
        TCGEN05_FENCE_BEFORE();
    }
    __syncthreads();
    if (wid == 0) TCGEN05_DEALLOC(tmem, 128);
#else
    for (int half = 0; half < 2; half++) {
        int rowbase = blockIdx.y * LTM + half * BM;
        gemm_tile<false, 256>(emb + (size_t)rowbase * KD, nullptr, BM, g_wlt,
                              g_left + (size_t)rowbase * JD, nullptr, 0, blockIdx.x);
        __syncthreads();
    }
#endif
}

// ---------------- grid barrier ----------------------------------------------
__device__ __forceinline__ void grid_barrier(unsigned target) {
    __syncthreads();
    if (threadIdx.x == 0) {
        __threadfence();
        unsigned arrived = atomicAdd(&g_bar_count, 1);
        if (arrived == gridDim.x - 1) {
            atomicExch(&g_bar_count, 0);
            __threadfence();
            atomicExch(&g_bar_epoch, target);
        } else {
            unsigned cur;
            do {
                asm volatile("ld.acquire.gpu.u32 %0, [%1];" : "=r"(cur) : "l"(&g_bar_epoch));
                if (cur >= target) break;
                __nanosleep(64);
            } while (true);
        }
    }
    __syncthreads();
}

// ---------------- persistent level-sweep kernel -------------------------------
// Per level L: (A) epilogue for all L-nodes (reads g_rw[parent], computed when the
// parent's level ran phase B); (B) right-GEMM (tcgen05 tf32, double-buffered) for
// INTERNAL L-nodes only: g_rw[nid] = h[nid] @ Wright^T (dedup: one row/parent).
// wo (transposed) and the phase-B tile buffers share the dynamic SMEM block.
__global__ __launch_bounds__(TLB) void tree_lstm_k(float* hout,
                                                   const float* __restrict__ wo,
                                                   const float* __restrict__ bias,
                                                   const float* __restrict__ wr,
                                                   const float* __restrict__ ur) {
    extern __shared__ char dynbuf[];
    __shared__ float pooled_s[TLB / 32][24];
    unsigned epoch = g_bar_epoch;   // carries across graph replays; uniform at entry
    int nlev = g_nlev;
    int tid  = threadIdx.x;
    int warp = tid >> 5, lane = tid & 31;
    int gw = blockIdx.x * (TLB / 32) + warp;
    int nw = gridDim.x * (TLB / 32);

    uint32_t raw = smem_u32(dynbuf);
    uint32_t base0 = (raw + 1023u) & ~1023u;
    char* dynA = dynbuf + (base0 - raw);
    // wo_t SMEM: [p][g*HD+h], conflict-free LDS (lane stride 4B)
    float* wot_s = (float*)(dynA + 4 * TILEB);
    for (int i = tid; i < WOT_FLOATS; i += TLB) wot_s[i] = g_wot[i];

#if HAS_TCGEN05
    __shared__ int s_idx[LTM];
    __shared__ uint32_t s_tmem;
    __shared__ __align__(8) unsigned long long s_mbar[2];
    uint32_t aB0 = base0,              bB0 = base0 + TILEB;
    uint32_t aB1 = base0 + 2 * TILEB,  bB1 = base0 + 3 * TILEB;
    char* aP0 = dynA;             char* bP0 = dynA + TILEB;
    char* aP1 = dynA + 2 * TILEB; char* bP1 = dynA + 3 * TILEB;
    uint32_t mb0 = smem_u32(&s_mbar[0]), mb1 = smem_u32(&s_mbar[1]);
    uint32_t tp = smem_u32(&s_tmem);
    if (warp == 0) { TCGEN05_ALLOC(tp, 128); TCGEN05_RELINQ(); }
    if (tid == 0) { MBARRIER_INIT(mb0, 1); MBARRIER_INIT(mb1, 1); }
    __syncthreads();
    uint32_t tmem;
    asm volatile("ld.shared.b32 %0, [%1];" : "=r"(tmem) : "r"(tp));
    uint64_t ad0 = MAKE_SMEM_DESC(aB0), bd0 = MAKE_SMEM_DESC(bB0);
    uint64_t ad1 = MAKE_SMEM_DESC(aB1), bd1 = MAKE_SMEM_DESC(bB1);
    int cnt0 = 0, cnt1 = 0;    // commits issued per mbar (uniform across threads)
#else
    __syncthreads();           // wo_t visible
#endif

    for (int lvl = 0; lvl < nlev; lvl++) {
        int base = g_off[lvl];
        int M    = g_off[lvl + 1] - base;

        // ---------------- Phase A: per-node epilogue (warp per node) ----------
        for (int i = gw; i < M; i += nw) {
            unsigned nid = g_nodeid[base + i];
            int pidx = g_parid[base + i];
            const float* Lrow = g_left + (size_t)nid * JD;

            if (pidx >= 0) {
                const float* Rrow = g_rw + (size_t)pidx * JD;
                // pooled[g,p] = sum_r lw*rw — 4 independent butterfly chains for ILP
#pragma unroll
                for (int gq = 0; gq < 24; gq += 4) {
                    float v0, v1, v2, v3;
                    { int o = (gq + 0) * 64 + lane; v0 = Lrow[o] * Rrow[o] + Lrow[o + 32] * Rrow[o + 32]; }
                    { int o = (gq + 1) * 64 + lane; v1 = Lrow[o] * Rrow[o] + Lrow[o + 32] * Rrow[o + 32]; }
                    { int o = (gq + 2) * 64 + lane; v2 = Lrow[o] * Rrow[o] + Lrow[o + 32] * Rrow[o + 32]; }
                    { int o = (gq + 3) * 64 + lane; v3 = Lrow[o] * Rrow[o] + Lrow[o + 32] * Rrow[o + 32]; }
#pragma unroll
                    for (int s = 16; s > 0; s >>= 1) {
                        v0 += __shfl_xor_sync(0xffffffffu, v0, s);
                        v1 += __shfl_xor_sync(0xffffffffu, v1, s);
                        v2 += __shfl_xor_sync(0xffffffffu, v2, s);
                        v3 += __shfl_xor_sync(0xffffffffu, v3, s);
                    }
                    if (lane == 0) {
                        pooled_s[warp][gq + 0] = v0;
                        pooled_s[warp][gq + 1] = v1;
                        pooled_s[warp][gq + 2] = v2;
                        pooled_s[warp][gq + 3] = v3;
                    }
                }
                __syncwarp();
                for (int hh = lane; hh < HD; hh += 32) {
                    float gv[3];
#pragma unroll
                    for (int g = 0; g < 3; g++) {
                        float acc = bias[g * HD + hh] + Lrow[1536 + g * HD + hh]
                                  + Rrow[1536 + g * HD + hh];
                        int gh = g * HD + hh;
#pragma unroll
                        for (int p = 0; p < 8; p++)
                            acc = fmaf(pooled_s[warp][g * 8 + p], wot_s[p * (3 * HD) + gh], acc);
                        gv[g] = acc;
                    }
                    float f  = fsigmoid(gv[0]);
                    float o_ = fsigmoid(gv[1]);
                    float z  = ftanh(gv[2]);
                    float pc = g_c[(size_t)pidx * HD + hh];
                    float c  = pc * f + (1.f - f) * z;
                    float h  = o_ * ftanh(c);
                    g_c[(size_t)nid * HD + hh]  = c;
                    hout[(size_t)nid * HD + hh] = h;
                }
                __syncwarp();   // pooled_s reuse
            } else {
                // root: parent h == 0 -> pooled = 0, right-linear = 0, pc = 0
                for (int hh = lane; hh < HD; hh += 32) {
                    float gv[3];
#pragma unroll
                    for (int g = 0; g < 3; g++)
                        gv[g] = bias[g * HD + hh] + Lrow[1536 + g * HD + hh];
                    float f  = fsigmoid(gv[0]);
                    float o_ = fsigmoid(gv[1]);
                    float z  = ftanh(gv[2]);
                    float c  = (1.f - f) * z;
                    float h  = o_ * ftanh(c);
                    g_c[(size_t)nid * HD + hh]  = c;
                    hout[(size_t)nid * HD + hh] = h;
                }
            }
        }
        epoch++; grid_barrier(epoch);

        // ---------------- Phase B: right-GEMM for internal nodes --------------
        int ibase = g_ioff[lvl];
        int Mi    = g_ioff[lvl + 1] - ibase;
        if (Mi > 0) {
#if HAS_TCGEN05
            int ntm = (Mi + LTM - 1) / LTM;
            int ntiles = ntm * NTN;
            for (int tile = blockIdx.x; tile < ntiles; tile += gridDim.x) {
                int tm = tile / NTN, tn = tile % NTN;
                int row0 = tm * LTM, col0 = tn * LTN;

                // cache gather indices for this tile
                if (tid < LTM) {
                    int r = row0 + tid;
                    s_idx[tid] = (r < Mi) ? g_iwork[ibase + r] : -1;
                }
                __syncthreads();

                auto load_chunk = [&](int c, char* aPtr, char* bPtr) {
                    int kc0 = c * LKC;
#pragma unroll
                    for (int i = 0; i < 2; i++) {
                        int f = tid + (i << 9);
                        int row = f >> 3, seg = f & 7;
                        int src_r = s_idx[row];
                        float4 v = make_float4(0.f, 0.f, 0.f, 0.f);
                        if (src_r >= 0)
                            v = *(const float4*)(hout + (size_t)src_r * KD + kc0 + seg * 4);
                        uint4 t = make_uint4(to_tf32(v.x), to_tf32(v.y), to_tf32(v.z), to_tf32(v.w));
                        *(uint4*)(aPtr + SMEM_SWIZZLE_128B(row * 128 + seg * 16)) = t;
                    }
#pragma unroll
                    for (int i = 0; i < 2; i++) {
                        int f = tid + (i << 9);
                        int row = f >> 3, seg = f & 7;
                        int j = col0 + row;
                        const float* src = (j < 1536) ? (wr + (size_t)j * KD)
                                                      : (ur + (size_t)(j - 1536) * KD);
                        float4 v = *(const float4*)(src + kc0 + seg * 4);
                        uint4 t = make_uint4(to_tf32(v.x), to_tf32(v.y), to_tf32(v.z), to_tf32(v.w));
                        *(uint4*)(bPtr + SMEM_SWIZZLE_128B(row * 128 + seg * 16)) = t;
                    }
                };

                for (int cp = 0; cp < LCHUNKS / 2; cp++) {
                    // even chunk -> buffer 0
                    if (cnt0 > 0) MBARRIER_WAIT_PARITY(mb0, (cnt0 - 1) & 1);
                    load_chunk(2 * cp, aP0, bP0);
                    __syncthreads();
                    FENCE_PROXY_ASYNC();
                    if (warp == 0 && elect_one_pred()) {
#pragma unroll
                        for (int s = 0; s < 4; s++)
                            mma_tf32_ss(tmem, ad0 + s * 2, bd0 + s * 2, LIDESC, (cp > 0) || (s > 0));
                        TCGEN05_COMMIT(mb0);
                    }
                    cnt0++;
                    // odd chunk -> buffer 1
                    if (cnt1 > 0) MBARRIER_WAIT_PARITY(mb1, (cnt1 - 1) & 1);
                    load_chunk(2 * cp + 1, aP1, bP1);
                    __syncthreads();
                    FENCE_PROXY_ASYNC();
                    if (warp == 0 && elect_one_pred()) {
#pragma unroll
                        for (int s = 0; s < 4; s++)
                            mma_tf32_ss(tmem, ad1 + s * 2, bd1 + s * 2, LIDESC, true);
                        TCGEN05_COMMIT(mb1);
                    }
                    cnt1++;
                }
                // last commit (mb1) covers all prior MMAs of this tile
                MBARRIER_WAIT_PARITY(mb1, (cnt1 - 1) & 1);
                TCGEN05_FENCE_AFTER();
                if (warp < 4) {
                    int row = warp * 32 + lane;
                    int dst_r = s_idx[row];
                    float* dst0 = (dst_r >= 0) ? (g_rw + (size_t)dst_r * JD + col0) : nullptr;
#pragma unroll
                    for (int cb = 0; cb < LTN; cb += 32) {
                        uint32_t d[32];
                        TCGEN05_LD_32X32B_X32(d, tmem + cb);
                        TCGEN05_WAIT_LD();
                        if (dst0) {
                            float4* dst4 = (float4*)(dst0 + cb);
#pragma unroll
                            for (int q = 0; q < 8; q++)
                                dst4[q] = make_float4(__uint_as_float(d[4 * q]),
                                                      __uint_as_float(d[4 * q + 1]),
                                                      __uint_as_float(d[4 * q + 2]),
                                                      __uint_as_float(d[4 * q + 3]));
                        }
                    }
                    TCGEN05_FENCE_BEFORE();
                }
                __syncthreads();   // TMEM reads + s_idx uses done before next tile
            }
#else
            int ntiles = ((Mi + BM - 1) / BM) * (JD / BN);
            for (int tile = blockIdx.x; tile < ntiles; tile += gridDim.x) {
                gemm_tile<true, TLB>(hout, g_iwork + ibase, Mi, g_wrt,
                                     g_rw, g_iwork + ibase, tile / (JD / BN), tile % (JD / BN));
            }
#endif
        }
        epoch++; grid_barrier(epoch);
    }
#if HAS_TCGEN05
    __syncthreads();
    if (warp == 0) TCGEN05_DEALLOC(tmem, 128);
#endif
}

// ---------------- launch ------------------------------------------------------
extern "C" void kernel_launch(void* const* d_in, const int* in_sizes, int n_in,
                              void* d_out, int out_size) {
    const float* emb    = (const float*)d_in[0];
    const int*   parent = (const int*)d_in[1];
    // d_in[2] = node_mask (unused, all ones)
    const float* wl   = (const float*)d_in[3];
    const float* wr   = (const float*)d_in[4];
    const float* wo   = (const float*)d_in[5];
    const float* ul   = (const float*)d_in[6];
    const float* ur   = (const float*)d_in[7];
    const float* bias = (const float*)d_in[8];
    float* hout = (float*)d_out;

    static int attr_done = 0;
    if (!attr_done) {
        cudaFuncSetAttribute(left_tc_k, cudaFuncAttributeMaxDynamicSharedMemorySize, DSMEM_LEFT);
        cudaFuncSetAttribute(tree_lstm_k, cudaFuncAttributeMaxDynamicSharedMemorySize, DSMEM_TREE);
        attr_done = 1;
    }

    pack_weights_k<<<(KD * JD + 255) / 256, 256>>>(wl, ul, wr, ur, wo);
    build_levels_k<<<1, 512>>>(parent);
    left_tc_k<<<dim3(JD / LTN, NTOT / LTM), 256, DSMEM_LEFT>>>(emb, wl, ul);
    tree_lstm_k<<<NCTA, TLB, DSMEM_TREE>>>(hout, wo, bias, wr, ur);
}

// round 16
// speedup vs baseline: 2.0736x; 1.2749x over previous
#include <cuda_runtime.h>
#include <cstdint>

// Problem constants
#define BB     128
#define NNODE  512
#define KD     512          // IN == HID == 512 (contraction dim)
#define HD     512
#define JD     3072         // 1536 bilinear (g,p,r) + 1536 linear (g,h)
#define NTOT   (BB * NNODE) // 65536 nodes

// SIMT GEMM tile config (fallback pass only)
#define BM     64
#define BN     128
#define BKT    16

// Persistent kernel shape
#define NCTA   148
#define TLB    512          // threads per block in tree_lstm (16 warps)

// Tensor-core GEMM tile (tf32)
#define LTM    128
#define LTN    128
#define LKC    32                 // K elements per chunk = 128 bytes (tf32)
#define LCHUNKS (KD / LKC)        // 16
#define NTN    (JD / LTN)         // 24 column tiles
#define TILEB  16384              // one 128x128B SMEM tile
#define WOT_FLOATS (3 * HD * 8)   // transposed wo: [p][g*HD+h]
#define WOT_BYTES  (WOT_FLOATS * 4)
#define DSMEM_LEFT (4 * TILEB + 1024)
#define DSMEM_TREE (4 * TILEB + WOT_BYTES + 1024)
// idesc: dtype F32=1 @bit4, atype TF32=2 @bit7, btype TF32=2 @bit10, N/8 @bit17, M/16 @bit24
#define LIDESC ((1u << 4) | (2u << 7) | (2u << 10) | ((LTN / 8u) << 17) | ((LTM / 16u) << 24))

// tcgen05 is only legal in the arch-SPECIFIC (sm_103a) compilation pass. The
// harness also runs a plain compute_103 ptxas pass, which rejects tcgen05
// outright — so every tcgen05 token must vanish from that pass.
#if defined(__CUDA_ARCH_FEAT_SM103_ALL) || defined(__CUDA_ARCH_FEAT_SM100_ALL) || \
    (defined(__CUDA_ARCH_SPECIFIC__) && (__CUDA_ARCH_SPECIFIC__ == 1030))
#define HAS_TCGEN05 1
#else
#define HAS_TCGEN05 0
#endif

// ---------------- device globals (no runtime allocation allowed) -------------
__device__ float g_left[(size_t)NTOT * JD];   // left projections, by node id
__device__ float g_rw[(size_t)NTOT * JD];     // right projections, BY NODE ID (dedup)
__device__ float g_c[(size_t)NTOT * HD];      // cell state, by node id
__device__ float g_wlt[KD * JD];              // Wleft  transposed [k][j] (SIMT fallback)
__device__ float g_wrt[KD * JD];              // Wright transposed [k][j] (SIMT fallback)
__device__ float g_wot[WOT_FLOATS];           // wo transposed: [p][g*HD+h]
__device__ int g_off[NNODE + 1];
__device__ int g_ioff[NNODE + 1];
__device__ int g_nlev;
__device__ unsigned g_nodeid[NTOT];           // worklist: flat node id b*N+t
__device__ int g_parid[NTOT];                 // worklist: flat parent id, -1 = root
__device__ int g_iwork[NTOT];                 // internal-node worklist (by level)
__device__ unsigned g_bar_count;              // grid barrier (self-resetting)
__device__ unsigned g_bar_epoch;              // monotonic across replays

// ---------------- generic helpers (legal on all passes) -----------------------
__device__ __forceinline__ uint32_t smem_u32(const void* p) {
    uint32_t a;
    asm("{ .reg .u64 t; cvta.to.shared.u64 t, %1; cvt.u32.u64 %0, t; }" : "=r"(a) : "l"(p));
    return a;
}
#define SMEM_SWIZZLE_128B(o) ((o) ^ (((o) >> 3) & 0x70))

// Fast activations: __expf-based, sign-safe; ~1e-6 rel err (noise vs tf32 4.5e-4)
__device__ __forceinline__ float fsigmoid(float x) { return 1.f / (1.f + __expf(-x)); }
__device__ __forceinline__ float ftanh(float x) {
    float t = __expf(-2.f * fabsf(x));
    return copysignf((1.f - t) / (1.f + t), x);
}

#if HAS_TCGEN05
__device__ __forceinline__ uint32_t elect_one_pred() {
    uint32_t p;
    asm volatile("{ .reg .pred p; elect.sync _|p, 0xFFFFFFFF; selp.b32 %0, 1, 0, p; }" : "=r"(p));
    return p;
}
__device__ __forceinline__ uint32_t to_tf32(float x) {
    uint32_t r; asm("cvt.rna.tf32.f32 %0, %1;" : "=r"(r) : "f"(x)); return r;
}

static constexpr uint64_t SMEM_DESC_BASE_SW128 =
    (uint64_t(2) << 61) | (uint64_t(1) << 46) | (uint64_t(64) << 32) | (uint64_t(1) << 16);
#define MAKE_SMEM_DESC(base) (SMEM_DESC_BASE_SW128 | ((uint64_t)((base) >> 4) & 0x3FFF))

#define TCGEN05_ALLOC(sres, n) \
    asm volatile("tcgen05.alloc.cta_group::1.sync.aligned.shared::cta.b32 [%0], %1;" \
                 :: "r"((uint32_t)(sres)), "r"((uint32_t)(n)) : "memory")
#define TCGEN05_DEALLOC(t, n) \
    asm volatile("tcgen05.dealloc.cta_group::1.sync.aligned.b32 %0, %1;" :: "r"(t), "r"((uint32_t)(n)))
#define TCGEN05_RELINQ() \
    asm volatile("tcgen05.relinquish_alloc_permit.cta_group::1.sync.aligned;")
#define TCGEN05_COMMIT(mb) \
    asm volatile("tcgen05.commit.cta_group::1.mbarrier::arrive::one.shared::cluster.b64 [%0];" \
                 :: "r"((uint32_t)(mb)) : "memory")
#define TCGEN05_FENCE_AFTER()  asm volatile("tcgen05.fence::after_thread_sync;" ::: "memory")
#define TCGEN05_FENCE_BEFORE() asm volatile("tcgen05.fence::before_thread_sync;" ::: "memory")
#define TCGEN05_WAIT_LD()      asm volatile("tcgen05.wait::ld.sync.aligned;" ::: "memory")
#define FENCE_PROXY_ASYNC()    asm volatile("fence.proxy.async.shared::cta;" ::: "memory")
#define MBARRIER_INIT(mb, c) \
    asm volatile("mbarrier.init.shared.b64 [%0], %1;" :: "r"((uint32_t)(mb)), "r"((uint32_t)(c)) : "memory")
#define MBARRIER_WAIT_PARITY(mb, ph) do { \
    uint32_t _m = (uint32_t)(mb), _p = (uint32_t)(ph), _d; \
    asm volatile("{ .reg .pred p; mbarrier.try_wait.parity.acquire.cta.shared::cta.b64 p, [%1], %2; selp.b32 %0, 1, 0, p; }" \
                 : "=r"(_d) : "r"(_m), "r"(_p) : "memory"); \
    if (!_d) { \
        asm volatile("{ .reg .pred P1; WL_%=: mbarrier.try_wait.parity.acquire.cta.shared::cta.b64 P1, [%0], %1, 0x989680; @P1 bra.uni WD_%=; bra.uni WL_%=; WD_%=: }" \
                     :: "r"(_m), "r"(_p) : "memory"); \
    } } while (0)

#define TCGEN05_LD_32X32B_X32(r, addr) \
    asm volatile("tcgen05.ld.sync.aligned.32x32b.x32.b32 " \
        "{%0, %1, %2, %3, %4, %5, %6, %7, %8, %9, %10, %11, %12, %13, %14, %15, " \
        " %16, %17, %18, %19, %20, %21, %22, %23, %24, %25, %26, %27, %28, %29, %30, %31}, [%32];" \
        : "=r"((r)[0]),  "=r"((r)[1]),  "=r"((r)[2]),  "=r"((r)[3]), \
          "=r"((r)[4]),  "=r"((r)[5]),  "=r"((r)[6]),  "=r"((r)[7]), \
          "=r"((r)[8]),  "=r"((r)[9]),  "=r"((r)[10]), "=r"((r)[11]), \
          "=r"((r)[12]), "=r"((r)[13]), "=r"((r)[14]), "=r"((r)[15]), \
          "=r"((r)[16]), "=r"((r)[17]), "=r"((r)[18]), "=r"((r)[19]), \
          "=r"((r)[20]), "=r"((r)[21]), "=r"((r)[22]), "=r"((r)[23]), \
          "=r"((r)[24]), "=r"((r)[25]), "=r"((r)[26]), "=r"((r)[27]), \
          "=r"((r)[28]), "=r"((r)[29]), "=r"((r)[30]), "=r"((r)[31]) \
        : "r"(addr))

__device__ __forceinline__ void mma_tf32_ss(uint32_t d, uint64_t ad, uint64_t bd,
                                            uint32_t idesc, bool acc) {
    uint32_t en = acc ? 1u : 0u, z = 0u;
    asm volatile(
        "{\n\t.reg .pred p;\n\tsetp.ne.u32 p, %6, 0;\n\t"
        "tcgen05.mma.cta_group::1.kind::tf32 [%0], %1, %2, %3, {%4, %4, %4, %4}, p;\n\t}"
        :: "r"(d), "l"(ad), "l"(bd), "r"(idesc), "r"(z), "r"(z), "r"(en) : "memory");
}
#endif  // HAS_TCGEN05

// ---------------- weight packing ----------------------------------------------
__global__ void pack_weights_k(const float* __restrict__ wl, const float* __restrict__ ul,
                               const float* __restrict__ wr, const float* __restrict__ ur,
                               const float* __restrict__ wo) {
    int idx = blockIdx.x * blockDim.x + threadIdx.x;
    if (idx < WOT_FLOATS) {
        int gh = idx >> 3, p = idx & 7;      // wo shape (3, HID, POOL) row-major
        g_wot[p * (3 * HD) + gh] = wo[idx];
    }
    if (idx >= KD * JD) return;
    int k = idx / JD, j = idx % JD;
    g_wlt[idx] = (j < 1536) ? wl[(size_t)j * KD + k] : ul[(size_t)(j - 1536) * KD + k];
    g_wrt[idx] = (j < 1536) ? wr[(size_t)j * KD + k] : ur[(size_t)(j - 1536) * KD + k];
}

// ---------------- level decomposition -----------------------------------------
// Single CTA of 128 threads (one per batch). All loop-carried state lives in
// per-thread local memory (L1-cached) and SMEM atomics — no global-latency
// dependency chains.
__global__ void build_levels_k(const int* __restrict__ parent) {
    __shared__ int s_count[NNODE], s_icount[NNODE], s_cursor[NNODE], s_icursor[NNODE];
    __shared__ int s_nlev;
    int tid = threadIdx.x;
    for (int i = tid; i < NNODE; i += blockDim.x) {
        s_count[i] = 0; s_icount[i] = 0; s_cursor[i] = 0; s_icursor[i] = 0;
    }
    if (tid == 0) s_nlev = 0;
    __syncthreads();

    unsigned short lvl[NNODE];      // per-thread local (L1-cached)
    unsigned hasch[NNODE / 32];     // haschild bitmask
    if (tid < BB) {
        int base = tid * NNODE;
#pragma unroll
        for (int i = 0; i < NNODE / 32; i++) hasch[i] = 0;
        lvl[0] = 0;
        atomicAdd(&s_count[0], 1);
        int mx = 0;
        for (int t = 1; t < NNODE; t++) {
            int p = parent[base + t];          // guaranteed p < t
            int L = (int)lvl[p] + 1;
            lvl[t] = (unsigned short)L;
            atomicAdd(&s_count[L], 1);
            hasch[p >> 5] |= 1u << (p & 31);
            if (L > mx) mx = L;
        }
        atomicMax(&s_nlev, mx + 1);
        for (int t = 0; t < NNODE; t++)
            if ((hasch[t >> 5] >> (t & 31)) & 1u) atomicAdd(&s_icount[lvl[t]], 1);
    }
    __syncthreads();
    if (tid == 0) {
        int s = 0, si = 0;
        for (int l = 0; l < NNODE; l++) {
            g_off[l] = s;  s  += s_count[l];
            g_ioff[l] = si; si += s_icount[l];
        }
        g_off[NNODE] = s; g_ioff[NNODE] = si;
        g_nlev = s_nlev;
    }
    __syncthreads();
    if (tid < BB) {
        int base = tid * NNODE;
        for (int t = 0; t < NNODE; t++) {
            int L = lvl[t];
            int pos = g_off[L] + atomicAdd(&s_cursor[L], 1);
            g_nodeid[pos] = (unsigned)(base + t);
            g_parid[pos]  = (t == 0) ? -1 : (base + parent[base + t]);
            if ((hasch[t >> 5] >> (t & 31)) & 1u) {
                int ip = g_ioff[L] + atomicAdd(&s_icursor[L], 1);
                g_iwork[ip] = base + t;
            }
        }
    }
}

// ---------------- SIMT GEMM tile (fallback pass only) -------------------------
#if !HAS_TCGEN05
template<bool GATHER, int NT>
__device__ __forceinline__ void gemm_tile(
    const float* Asrc, const int* rows, int M,
    const float* __restrict__ Bt, float* Cout, const int* outrows, int tm, int tn) {
    __shared__ float As[BKT][BM + 4];
    __shared__ float Bs[BKT][BN];
    int tid = threadIdx.x;
    if (tid >= 256) { for (int k0 = 0; k0 < KD; k0 += BKT) { __syncthreads(); __syncthreads(); } return; }
    int tx = tid & 15, ty = tid >> 4;
    int row0 = tm * BM, col0 = tn * BN;

    float acc[4][8];
#pragma unroll
    for (int m = 0; m < 4; m++)
#pragma unroll
        for (int n = 0; n < 8; n++) acc[m][n] = 0.f;

    int arow = tid >> 2;
    int akq  = (tid & 3) * 4;
    const float* aptr = nullptr;
    {
        int r = row0 + arow;
        if (GATHER) {
            int p = (r < M) ? rows[r] : -1;
            if (p >= 0) aptr = Asrc + (size_t)p * KD;
        } else {
            if (r < M) aptr = Asrc + (size_t)r * KD;
        }
    }

    for (int k0 = 0; k0 < KD; k0 += BKT) {
        float4 av = make_float4(0.f, 0.f, 0.f, 0.f);
        if (aptr) av = *(const float4*)(aptr + k0 + akq);
        As[akq + 0][arow] = av.x;
        As[akq + 1][arow] = av.y;
        As[akq + 2][arow] = av.z;
        As[akq + 3][arow] = av.w;
#pragma unroll
        for (int i = 0; i < 2; i++) {
            int f  = tid + i * 256;
            int bk = f >> 5;
            int c4 = (f & 31) * 4;
            *(float4*)&Bs[bk][c4] = *(const float4*)(Bt + (size_t)(k0 + bk) * JD + col0 + c4);
        }
        __syncthreads();
#pragma unroll
        for (int k = 0; k < BKT; k++) {
            float a[4], b[8];
            *(float4*)a       = *(const float4*)&As[k][ty * 4];
            *(float4*)b       = *(const float4*)&Bs[k][tx * 8];
            *(float4*)(b + 4) = *(const float4*)&Bs[k][tx * 8 + 4];
#pragma unroll
            for (int m = 0; m < 4; m++)
#pragma unroll
                for (int n = 0; n < 8; n++) acc[m][n] = fmaf(a[m], b[n], acc[m][n]);
        }
        __syncthreads();
    }

#pragma unroll
    for (int m = 0; m < 4; m++) {
        int r = row0 + ty * 4 + m;
        if (r < M) {
            int orow = outrows ? outrows[r] : r;
            float* cp = Cout + (size_t)orow * JD + col0 + tx * 8;
            *(float4*)cp       = make_float4(acc[m][0], acc[m][1], acc[m][2], acc[m][3]);
            *(float4*)(cp + 4) = make_float4(acc[m][4], acc[m][5], acc[m][6], acc[m][7]);
        }
    }
}
#endif

// ---------------- LEFT projection GEMM ----------------------------------------
// out[node, j] = sum_k emb[node,k] * W[j,k], W rows = wl (j<1536) / ul (j>=1536).
// Double-buffered: load chunk c+1 while MMA of chunk c runs (2 mbars, 1/buffer).
__global__ __launch_bounds__(256, 2) void left_tc_k(const float* __restrict__ emb,
                                                    const float* __restrict__ wl,
                                                    const float* __restrict__ ul) {
#if HAS_TCGEN05
    extern __shared__ char dynbuf[];
    __shared__ uint32_t s_tmem;
    __shared__ __align__(8) unsigned long long s_mbar[2];

    int tid = threadIdx.x;
    int wid = tid >> 5, lane = tid & 31;
    int row0 = blockIdx.y * LTM;      // node rows
    int col0 = blockIdx.x * LTN;      // j cols

    uint32_t raw = smem_u32(dynbuf);
    uint32_t base0 = (raw + 1023u) & ~1023u;
    uint32_t aB0 = base0,              bB0 = base0 + TILEB;
    uint32_t aB1 = base0 + 2 * TILEB,  bB1 = base0 + 3 * TILEB;
    char* aP0 = dynbuf + (aB0 - raw); char* bP0 = dynbuf + (bB0 - raw);
    char* aP1 = dynbuf + (aB1 - raw); char* bP1 = dynbuf + (bB1 - raw);
    uint32_t mb0 = smem_u32(&s_mbar[0]), mb1 = smem_u32(&s_mbar[1]);
    uint32_t tp = smem_u32(&s_tmem);

    if (wid == 0) { TCGEN05_ALLOC(tp, 128); TCGEN05_RELINQ(); }
    if (tid == 0) { MBARRIER_INIT(mb0, 1); MBARRIER_INIT(mb1, 1); }
    __syncthreads();
    uint32_t tmem;
    asm volatile("ld.shared.b32 %0, [%1];" : "=r"(tmem) : "r"(tp));

    uint64_t ad0 = MAKE_SMEM_DESC(aB0), bd0 = MAKE_SMEM_DESC(bB0);
    uint64_t ad1 = MAKE_SMEM_DESC(aB1), bd1 = MAKE_SMEM_DESC(bB1);

    auto load_chunk = [&](int c, char* aPtr, char* bPtr) {
        int kc0 = c * LKC;
#pragma unroll
        for (int i = 0; i < 4; i++) {
            int f = tid + (i << 8);
            int row = f >> 3, seg = f & 7;
            float4 v = *(const float4*)(emb + (size_t)(row0 + row) * KD + kc0 + seg * 4);
            uint4 t = make_uint4(to_tf32(v.x), to_tf32(v.y), to_tf32(v.z), to_tf32(v.w));
            *(uint4*)(aPtr + SMEM_SWIZZLE_128B(row * 128 + seg * 16)) = t;
        }
#pragma unroll
        for (int i = 0; i < 4; i++) {
            int f = tid + (i << 8);
            int row = f >> 3, seg = f & 7;
            int j = col0 + row;
            const float* src = (j < 1536) ? (wl + (size_t)j * KD) : (ul + (size_t)(j - 1536) * KD);
            float4 v = *(const float4*)(src + kc0 + seg * 4);
            uint4 t = make_uint4(to_tf32(v.x), to_tf32(v.y), to_tf32(v.z), to_tf32(v.w));
            *(uint4*)(bPtr + SMEM_SWIZZLE_128B(row * 128 + seg * 16)) = t;
        }
    };

    for (int cp = 0; cp < LCHUNKS / 2; cp++) {
        // even chunk on buffer 0
        if (cp > 0) MBARRIER_WAIT_PARITY(mb0, (cp - 1) & 1);
        load_chunk(2 * cp, aP0, bP0);
        __syncthreads();
        FENCE_PROXY_ASYNC();
        if (wid == 0 && elect_one_pred()) {
#pragma unroll
            for (int s = 0; s < 4; s++)
                mma_tf32_ss(tmem, ad0 + s * 2, bd0 + s * 2, LIDESC, (cp > 0) || (s > 0));
            TCGEN05_COMMIT(mb0);
        }
        // odd chunk on buffer 1
        if (cp > 0) MBARRIER_WAIT_PARITY(mb1, (cp - 1) & 1);
        load_chunk(2 * cp + 1, aP1, bP1);
        __syncthreads();
        FENCE_PROXY_ASYNC();
        if (wid == 0 && elect_one_pred()) {
#pragma unroll
            for (int s = 0; s < 4; s++)
                mma_tf32_ss(tmem, ad1 + s * 2, bd1 + s * 2, LIDESC, true);
            TCGEN05_COMMIT(mb1);
        }
    }
    // last commit (mb1, count LCHUNKS/2) covers ALL prior MMAs
    MBARRIER_WAIT_PARITY(mb1, (LCHUNKS / 2 - 1) & 1);
    TCGEN05_FENCE_AFTER();

    if (wid < 4) {
        int r = row0 + wid * 32 + lane;
        float* dst0 = g_left + (size_t)r * JD + col0;
#pragma unroll
        for (int cb = 0; cb < LTN; cb += 32) {
            uint32_t d[32];
            TCGEN05_LD_32X32B_X32(d, tmem + cb);
            TCGEN05_WAIT_LD();
            float4* dst4 = (float4*)(dst0 + cb);
#pragma unroll
            for (int q = 0; q < 8; q++)
                dst4[q] = make_float4(__uint_as_float(d[4 * q]), __uint_as_float(d[4 * q + 1]),
                                      __uint_as_float(d[4 * q + 2]), __uint_as_float(d[4 * q + 3]));
        }
        TCGEN05_FENCE_BEFORE();
    }
    __syncthreads();
    if (wid == 0) TCGEN05_DEALLOC(tmem, 128);
#else
    for (int half = 0; half < 2; half++) {
        int rowbase = blockIdx.y * LTM + half * BM;
        gemm_tile<false, 256>(emb + (size_t)rowbase * KD, nullptr, BM, g_wlt,
                              g_left + (size_t)rowbase * JD, nullptr, 0, blockIdx.x);
        __syncthreads();
    }
#endif
}

// ---------------- grid barrier ----------------------------------------------
__device__ __forceinline__ void grid_barrier(unsigned target) {
    __syncthreads();
    if (threadIdx.x == 0) {
        __threadfence();
        unsigned arrived = atomicAdd(&g_bar_count, 1);
        if (arrived == gridDim.x - 1) {
            atomicExch(&g_bar_count, 0);
            __threadfence();
            atomicExch(&g_bar_epoch, target);
        } else {
            unsigned cur;
            do {
                asm volatile("ld.acquire.gpu.u32 %0, [%1];" : "=r"(cur) : "l"(&g_bar_epoch));
                if (cur >= target) break;
                __nanosleep(64);
            } while (true);
        }
    }
    __syncthreads();
}

// ---------------- persistent level-sweep kernel -------------------------------
// Per level L: (A) epilogue for all L-nodes (reads g_rw[parent], computed when the
// parent's level ran phase B); (B) right-GEMM (tcgen05 tf32, double-buffered) for
// INTERNAL L-nodes only: g_rw[nid] = h[nid] @ Wright^T (dedup: one row/parent).
// wo (transposed) and the phase-B tile buffers share the dynamic SMEM block.
__global__ __launch_bounds__(TLB) void tree_lstm_k(float* hout,
                                                   const float* __restrict__ wo,
                                                   const float* __restrict__ bias,
                                                   const float* __restrict__ wr,
                                                   const float* __restrict__ ur) {
    extern __shared__ char dynbuf[];
    __shared__ float pooled_s[TLB / 32][24];
    unsigned epoch = g_bar_epoch;   // carries across graph replays; uniform at entry
    int nlev = g_nlev;
    int tid  = threadIdx.x;
    int warp = tid >> 5, lane = tid & 31;
    int gw = blockIdx.x * (TLB / 32) + warp;
    int nw = gridDim.x * (TLB / 32);

    uint32_t raw = smem_u32(dynbuf);
    uint32_t base0 = (raw + 1023u) & ~1023u;
    char* dynA = dynbuf + (base0 - raw);
    // wo_t SMEM: [p][g*HD+h], conflict-free LDS (lane stride 16B, float4)
    float* wot_s = (float*)(dynA + 4 * TILEB);
    for (int i = tid; i < WOT_FLOATS; i += TLB) wot_s[i] = g_wot[i];

#if HAS_TCGEN05
    __shared__ int s_idx[LTM];
    __shared__ uint32_t s_tmem;
    __shared__ __align__(8) unsigned long long s_mbar[2];
    uint32_t aB0 = base0,              bB0 = base0 + TILEB;
    uint32_t aB1 = base0 + 2 * TILEB,  bB1 = base0 + 3 * TILEB;
    char* aP0 = dynA;             char* bP0 = dynA + TILEB;
    char* aP1 = dynA + 2 * TILEB; char* bP1 = dynA + 3 * TILEB;
    uint32_t mb0 = smem_u32(&s_mbar[0]), mb1 = smem_u32(&s_mbar[1]);
    uint32_t tp = smem_u32(&s_tmem);
    if (warp == 0) { TCGEN05_ALLOC(tp, 128); TCGEN05_RELINQ(); }
    if (tid == 0) { MBARRIER_INIT(mb0, 1); MBARRIER_INIT(mb1, 1); }
    __syncthreads();
    uint32_t tmem;
    asm volatile("ld.shared.b32 %0, [%1];" : "=r"(tmem) : "r"(tp));
    uint64_t ad0 = MAKE_SMEM_DESC(aB0), bd0 = MAKE_SMEM_DESC(bB0);
    uint64_t ad1 = MAKE_SMEM_DESC(aB1), bd1 = MAKE_SMEM_DESC(bB1);
    int cnt0 = 0, cnt1 = 0;    // commits issued per mbar (uniform across threads)
#else
    __syncthreads();           // wo_t visible
#endif

    for (int lvl = 0; lvl < nlev; lvl++) {
        int base = g_off[lvl];
        int M    = g_off[lvl + 1] - base;

        // ---------------- Phase A: per-node epilogue (warp per node) ----------
        for (int i = gw; i < M; i += nw) {
            unsigned nid = g_nodeid[base + i];
            int pidx = g_parid[base + i];
            const float* Lrow = g_left + (size_t)nid * JD;

            if (pidx >= 0) {
                const float* Rrow = g_rw + (size_t)pidx * JD;
                // pooled[g,p] = sum_r lw*rw — float2 loads (lane covers ranks 2l,2l+1),
                // 4 independent butterfly chains for ILP
#pragma unroll
                for (int gq = 0; gq < 24; gq += 4) {
                    float v0, v1, v2, v3;
                    {
                        float2 l2 = *(const float2*)(Lrow + (gq + 0) * 64 + 2 * lane);
                        float2 r2 = *(const float2*)(Rrow + (gq + 0) * 64 + 2 * lane);
                        v0 = l2.x * r2.x + l2.y * r2.y;
                    }
                    {
                        float2 l2 = *(const float2*)(Lrow + (gq + 1) * 64 + 2 * lane);
                        float2 r2 = *(const float2*)(Rrow + (gq + 1) * 64 + 2 * lane);
                        v1 = l2.x * r2.x + l2.y * r2.y;
                    }
                    {
                        float2 l2 = *(const float2*)(Lrow + (gq + 2) * 64 + 2 * lane);
                        float2 r2 = *(const float2*)(Rrow + (gq + 2) * 64 + 2 * lane);
                        v2 = l2.x * r2.x + l2.y * r2.y;
                    }
                    {
                        float2 l2 = *(const float2*)(Lrow + (gq + 3) * 64 + 2 * lane);
                        float2 r2 = *(const float2*)(Rrow + (gq + 3) * 64 + 2 * lane);
                        v3 = l2.x * r2.x + l2.y * r2.y;
                    }
#pragma unroll
                    for (int s = 16; s > 0; s >>= 1) {
                        v0 += __shfl_xor_sync(0xffffffffu, v0, s);
                        v1 += __shfl_xor_sync(0xffffffffu, v1, s);
                        v2 += __shfl_xor_sync(0xffffffffu, v2, s);
                        v3 += __shfl_xor_sync(0xffffffffu, v3, s);
                    }
                    if (lane == 0) {
                        pooled_s[warp][gq + 0] = v0;
                        pooled_s[warp][gq + 1] = v1;
                        pooled_s[warp][gq + 2] = v2;
                        pooled_s[warp][gq + 3] = v3;
                    }
                }
                __syncwarp();
                // hh loop vectorized: 4 iterations x float4 per lane (128 h/warp/iter)
#pragma unroll
                for (int q = 0; q < 4; q++) {
                    int hh = q * 128 + lane * 4;
                    float4 gv[3];
#pragma unroll
                    for (int g = 0; g < 3; g++) {
                        int gh = g * HD + hh;
                        float4 b4 = *(const float4*)(bias + gh);
                        float4 l4 = *(const float4*)(Lrow + 1536 + gh);
                        float4 r4 = *(const float4*)(Rrow + 1536 + gh);
                        float4 acc = make_float4(b4.x + l4.x + r4.x, b4.y + l4.y + r4.y,
                                                 b4.z + l4.z + r4.z, b4.w + l4.w + r4.w);
#pragma unroll
                        for (int p = 0; p < 8; p++) {
                            float pw = pooled_s[warp][g * 8 + p];
                            float4 w4 = *(const float4*)(wot_s + p * (3 * HD) + gh);
                            acc.x = fmaf(pw, w4.x, acc.x);
                            acc.y = fmaf(pw, w4.y, acc.y);
                            acc.z = fmaf(pw, w4.z, acc.z);
                            acc.w = fmaf(pw, w4.w, acc.w);
                        }
                        gv[g] = acc;
                    }
                    float4 pc4 = *(const float4*)(g_c + (size_t)pidx * HD + hh);
                    float4 c4, h4;
                    {
                        float f = fsigmoid(gv[0].x), o_ = fsigmoid(gv[1].x), z = ftanh(gv[2].x);
                        c4.x = pc4.x * f + (1.f - f) * z;  h4.x = o_ * ftanh(c4.x);
                    }
                    {
                        float f = fsigmoid(gv[0].y), o_ = fsigmoid(gv[1].y), z = ftanh(gv[2].y);
                        c4.y = pc4.y * f + (1.f - f) * z;  h4.y = o_ * ftanh(c4.y);
                    }
                    {
                        float f = fsigmoid(gv[0].z), o_ = fsigmoid(gv[1].z), z = ftanh(gv[2].z);
                        c4.z = pc4.z * f + (1.f - f) * z;  h4.z = o_ * ftanh(c4.z);
                    }
                    {
                        float f = fsigmoid(gv[0].w), o_ = fsigmoid(gv[1].w), z = ftanh(gv[2].w);
                        c4.w = pc4.w * f + (1.f - f) * z;  h4.w = o_ * ftanh(c4.w);
                    }
                    *(float4*)(g_c + (size_t)nid * HD + hh)  = c4;
                    *(float4*)(hout + (size_t)nid * HD + hh) = h4;
                }
                __syncwarp();   // pooled_s reuse
            } else {
                // root: parent h == 0 -> pooled = 0, right-linear = 0, pc = 0
#pragma unroll
                for (int q = 0; q < 4; q++) {
                    int hh = q * 128 + lane * 4;
                    float4 gv[3];
#pragma unroll
                    for (int g = 0; g < 3; g++) {
                        int gh = g * HD + hh;
                        float4 b4 = *(const float4*)(bias + gh);
                        float4 l4 = *(const float4*)(Lrow + 1536 + gh);
                        gv[g] = make_float4(b4.x + l4.x, b4.y + l4.y, b4.z + l4.z, b4.w + l4.w);
                    }
                    float4 c4, h4;
                    {
                        float f = fsigmoid(gv[0].x), o_ = fsigmoid(gv[1].x), z = ftanh(gv[2].x);
                        c4.x = (1.f - f) * z;  h4.x = o_ * ftanh(c4.x);
                    }
                    {
                        float f = fsigmoid(gv[0].y), o_ = fsigmoid(gv[1].y), z = ftanh(gv[2].y);
                        c4.y = (1.f - f) * z;  h4.y = o_ * ftanh(c4.y);
                    }
                    {
                        float f = fsigmoid(gv[0].z), o_ = fsigmoid(gv[1].z), z = ftanh(gv[2].z);
                        c4.z = (1.f - f) * z;  h4.z = o_ * ftanh(c4.z);
                    }
                    {
                        float f = fsigmoid(gv[0].w), o_ = fsigmoid(gv[1].w), z = ftanh(gv[2].w);
                        c4.w = (1.f - f) * z;  h4.w = o_ * ftanh(c4.w);
                    }
                    *(float4*)(g_c + (size_t)nid * HD + hh)  = c4;
                    *(float4*)(hout + (size_t)nid * HD + hh) = h4;
                }
            }
        }
        epoch++; grid_barrier(epoch);

        // ---------------- Phase B: right-GEMM for internal nodes --------------
        int ibase = g_ioff[lvl];
        int Mi    = g_ioff[lvl + 1] - ibase;
        if (Mi > 0) {
#if HAS_TCGEN05
            int ntm = (Mi + LTM - 1) / LTM;
            int ntiles = ntm * NTN;
            for (int tile = blockIdx.x; tile < ntiles; tile += gridDim.x) {
                int tm = tile / NTN, tn = tile % NTN;
                int row0 = tm * LTM, col0 = tn * LTN;

                // cache gather indices for this tile
                if (tid < LTM) {
                    int r = row0 + tid;
                    s_idx[tid] = (r < Mi) ? g_iwork[ibase + r] : -1;
                }
                __syncthreads();

                auto load_chunk = [&](int c, char* aPtr, char* bPtr) {
                    int kc0 = c * LKC;
#pragma unroll
                    for (int i = 0; i < 2; i++) {
                        int f = tid + (i << 9);
                        int row = f >> 3, seg = f & 7;
                        int src_r = s_idx[row];
                        float4 v = make_float4(0.f, 0.f, 0.f, 0.f);
                        if (src_r >= 0)
                            v = *(const float4*)(hout + (size_t)src_r * KD + kc0 + seg * 4);
                        uint4 t = make_uint4(to_tf32(v.x), to_tf32(v.y), to_tf32(v.z), to_tf32(v.w));
                        *(uint4*)(aPtr + SMEM_SWIZZLE_128B(row * 128 + seg * 16)) = t;
                    }
#pragma unroll
                    for (int i = 0; i < 2; i++) {
                        int f = tid + (i << 9);
                        int row = f >> 3, seg = f & 7;
                        int j = col0 + row;
                        const float* src = (j < 1536) ? (wr + (size_t)j * KD)
                                                      : (ur + (size_t)(j - 1536) * KD);
                        float4 v = *(const float4*)(src + kc0 + seg * 4);
                        uint4 t = make_uint4(to_tf32(v.x), to_tf32(v.y), to_tf32(v.z), to_tf32(v.w));
                        *(uint4*)(bPtr + SMEM_SWIZZLE_128B(row * 128 + seg * 16)) = t;
                    }
                };

                for (int cp = 0; cp < LCHUNKS / 2; cp++) {
                    // even chunk -> buffer 0
                    if (cnt0 > 0) MBARRIER_WAIT_PARITY(mb0, (cnt0 - 1) & 1);
                    load_chunk(2 * cp, aP0, bP0);
                    __syncthreads();
                    FENCE_PROXY_ASYNC();
                    if (warp == 0 && elect_one_pred()) {
#pragma unroll
                        for (int s = 0; s < 4; s++)
                            mma_tf32_ss(tmem, ad0 + s * 2, bd0 + s * 2, LIDESC, (cp > 0) || (s > 0));
                        TCGEN05_COMMIT(mb0);
                    }
                    cnt0++;
                    // odd chunk -> buffer 1
                    if (cnt1 > 0) MBARRIER_WAIT_PARITY(mb1, (cnt1 - 1) & 1);
                    load_chunk(2 * cp + 1, aP1, bP1);
                    __syncthreads();
                    FENCE_PROXY_ASYNC();
                    if (warp == 0 && elect_one_pred()) {
#pragma unroll
                        for (int s = 0; s < 4; s++)
                            mma_tf32_ss(tmem, ad1 + s * 2, bd1 + s * 2, LIDESC, true);
                        TCGEN05_COMMIT(mb1);
                    }
                    cnt1++;
                }
                // last commit (mb1) covers all prior MMAs of this tile
                MBARRIER_WAIT_PARITY(mb1, (cnt1 - 1) & 1);
                TCGEN05_FENCE_AFTER();
                if (warp < 4) {
                    int row = warp * 32 + lane;
                    int dst_r = s_idx[row];
                    float* dst0 = (dst_r >= 0) ? (g_rw + (size_t)dst_r * JD + col0) : nullptr;
#pragma unroll
                    for (int cb = 0; cb < LTN; cb += 32) {
                        uint32_t d[32];
                        TCGEN05_LD_32X32B_X32(d, tmem + cb);
                        TCGEN05_WAIT_LD();
                        if (dst0) {
                            float4* dst4 = (float4*)(dst0 + cb);
#pragma unroll
                            for (int q = 0; q < 8; q++)
                                dst4[q] = make_float4(__uint_as_float(d[4 * q]),
                                                      __uint_as_float(d[4 * q + 1]),
                                                      __uint_as_float(d[4 * q + 2]),
                                                      __uint_as_float(d[4 * q + 3]));
                        }
                    }
                    TCGEN05_FENCE_BEFORE();
                }
                __syncthreads();   // TMEM reads + s_idx uses done before next tile
            }
#else
            int ntiles = ((Mi + BM - 1) / BM) * (JD / BN);
            for (int tile = blockIdx.x; tile < ntiles; tile += gridDim.x) {
                gemm_tile<true, TLB>(hout, g_iwork + ibase, Mi, g_wrt,
                                     g_rw, g_iwork + ibase, tile / (JD / BN), tile % (JD / BN));
            }
#endif
        }
        epoch++; grid_barrier(epoch);
    }
#if HAS_TCGEN05
    __syncthreads();
    if (warp == 0) TCGEN05_DEALLOC(tmem, 128);
#endif
}

// ---------------- launch ------------------------------------------------------
extern "C" void kernel_launch(void* const* d_in, const int* in_sizes, int n_in,
                              void* d_out, int out_size) {
    const float* emb    = (const float*)d_in[0];
    const int*   parent = (const int*)d_in[1];
    // d_in[2] = node_mask (unused, all ones)
    const float* wl   = (const float*)d_in[3];
    const float* wr   = (const float*)d_in[4];
    const float* wo   = (const float*)d_in[5];
    const float* ul   = (const float*)d_in[6];
    const float* ur   = (const float*)d_in[7];
    const float* bias = (const float*)d_in[8];
    float* hout = (float*)d_out;

    static int attr_done = 0;
    if (!attr_done) {
        cudaFuncSetAttribute(left_tc_k, cudaFuncAttributeMaxDynamicSharedMemorySize, DSMEM_LEFT);
        cudaFuncSetAttribute(tree_lstm_k, cudaFuncAttributeMaxDynamicSharedMemorySize, DSMEM_TREE);
        attr_done = 1;
    }

    pack_weights_k<<<(KD * JD + 255) / 256, 256>>>(wl, ul, wr, ur, wo);
    build_levels_k<<<1, 128>>>(parent);
    left_tc_k<<<dim3(JD / LTN, NTOT / LTM), 256, DSMEM_LEFT>>>(emb, wl, ul);
    tree_lstm_k<<<NCTA, TLB, DSMEM_TREE>>>(hout, wo, bias, wr, ur);
}